// round 13
// baseline (speedup 1.0000x reference)
#include <cuda_runtime.h>
#include <cuda_bf16.h>
#include <cstdint>

#define BS 128
#define NN 32
#define IN_DIM 16
#define HID 128
#define HEADS 4
#define OUTD 5
#define DUEL_H 256
#define D1 (HEADS*HID)       // 512
#define LATENT (HID + 2*D1)  // 1152
#define OBS_W (NN*(2+IN_DIM)+1) // 577
#define RAD2 0.09f

typedef unsigned int uint;
typedef __nv_bfloat16 bf16;

// -------- scratch (device globals; no runtime alloc allowed) --------
__device__ float g_X0 [BS*NN*HID];
__device__ int      g_POFF [BS*33];
__device__ unsigned short g_PAIRS[BS*NN*NN];
__device__ float g_GL1[BS*NN*D1];
__device__ float g_GR1[BS*NN*D1];
__device__ float g_X1 [BS*NN*D1];
__device__ float g_GL2[BS*NN*D1];
__device__ float g_GR2[BS*NN*D1];
__device__ float g_X2 [BS*NN*D1];
__device__ float g_QH [BS*DUEL_H];
__device__ float g_VH [BS*DUEL_H];
// bf16 hi/lo splits
__device__ bf16 g_X0h[BS*NN*HID],  g_X0l[BS*NN*HID];
__device__ bf16 g_X1h[BS*NN*D1],   g_X1l[BS*NN*D1];
__device__ bf16 g_wl1h[HID*D1], g_wl1l[HID*D1], g_wr1h[HID*D1], g_wr1l[HID*D1];
__device__ bf16 g_wl2h[D1*D1],  g_wl2l[D1*D1],  g_wr2h[D1*D1],  g_wr2l[D1*D1];

__device__ __forceinline__ uint32_t sptr(const void* p) {
    return (uint32_t)__cvta_generic_to_shared(p);
}
__device__ __forceinline__ void split_store(float v, bf16* hp, bf16* lp, size_t idx) {
    bf16 h = __float2bfloat16(v);
    hp[idx] = h;
    lp[idx] = __float2bfloat16(v - __bfloat162float(h));
}
__device__ __forceinline__ void ldsm_x4(uint4& d, uint32_t a) {
    asm volatile("ldmatrix.sync.aligned.m8n8.x4.shared.b16 {%0,%1,%2,%3}, [%4];"
        : "=r"(d.x), "=r"(d.y), "=r"(d.z), "=r"(d.w) : "r"(a));
}
__device__ __forceinline__ void ldsm_x4t(uint4& d, uint32_t a) {
    asm volatile("ldmatrix.sync.aligned.m8n8.x4.trans.shared.b16 {%0,%1,%2,%3}, [%4];"
        : "=r"(d.x), "=r"(d.y), "=r"(d.z), "=r"(d.w) : "r"(a));
}
__device__ __forceinline__ void mma_bf16(float* d,
                                         uint a0, uint a1, uint a2, uint a3,
                                         uint b0, uint b1)
{
    asm("mma.sync.aligned.m16n8k16.row.col.f32.bf16.bf16.f32 "
        "{%0,%1,%2,%3}, {%4,%5,%6,%7}, {%8,%9}, {%0,%1,%2,%3};"
        : "+f"(d[0]), "+f"(d[1]), "+f"(d[2]), "+f"(d[3])
        : "r"(a0), "r"(a1), "r"(a2), "r"(a3), "r"(b0), "r"(b1));
}

// -------- split all 4 weight matrices into bf16 hi/lo --------
__global__ void split_w_k(const float* __restrict__ wl1, const float* __restrict__ wr1,
                          const float* __restrict__ wl2, const float* __restrict__ wr2)
{
    int i = blockIdx.x*256 + threadIdx.x;
    const int S1 = HID*D1;
    const int S2 = D1*D1;
    if (i < S1)                   split_store(wl1[i],        g_wl1h, g_wl1l, i);
    else if (i < 2*S1)            split_store(wr1[i-S1],     g_wr1h, g_wr1l, i-S1);
    else if (i < 2*S1+S2)         split_store(wl2[i-2*S1],   g_wl2h, g_wl2l, i-2*S1);
    else                          split_store(wr2[i-2*S1-S2],g_wr2h, g_wr2l, i-2*S1-S2);
}

// -------- encoder + adjacency pair list: one block per batch --------
__global__ void enc_kernel(const float* __restrict__ obs,
                           const float* __restrict__ w1, const float* __restrict__ b1,
                           const float* __restrict__ w2, const float* __restrict__ b2,
                           float* __restrict__ X0, bf16* __restrict__ X0h,
                           bf16* __restrict__ X0l,
                           int* __restrict__ POFF, unsigned short* __restrict__ PAIRS)
{
    __shared__ float s_obs[OBS_W];
    __shared__ float s_h[NN*HID];
    int b = blockIdx.x, t = threadIdx.x;

    for (int i = t; i < OBS_W; i += 128) s_obs[i] = obs[b*OBS_W + i];
    __syncthreads();

    if (t < NN) {
        float xi = s_obs[t*18 + 0], yi = s_obs[t*18 + 1];
        unsigned m = 0;
        #pragma unroll
        for (int j = 0; j < NN; j++) {
            float dx = xi - s_obs[j*18 + 0];
            float dy = yi - s_obs[j*18 + 1];
            float d2 = dx*dx + dy*dy;
            if (d2 < RAD2 || j == t) m |= (1u << j);
        }
        int c = __popc(m);
        int sc = c;
        #pragma unroll
        for (int o = 1; o < 32; o <<= 1) {
            int v = __shfl_up_sync(0xffffffffu, sc, o);
            if (t >= o) sc += v;
        }
        int off = sc - c;
        POFF[b*33 + t] = off;
        if (t == 31) POFF[b*33 + 32] = off + c;
        int k = off;
        unsigned mm = m;
        while (mm) {
            int jj = __ffs(mm) - 1;
            mm &= mm - 1;
            PAIRS[b*NN*NN + k++] = (unsigned short)((t << 5) | jj);
        }
    }

    float bb = b1[t];
    for (int r = 0; r < NN; r++) {
        float acc = bb;
        #pragma unroll
        for (int f = 0; f < IN_DIM; f++)
            acc += s_obs[r*18 + 2 + f] * w1[f*HID + t];
        s_h[r*HID + t] = fmaxf(acc, 0.f);
    }
    __syncthreads();

    float acc2[NN];
    float b2v = b2[t];
    #pragma unroll
    for (int r = 0; r < NN; r++) acc2[r] = b2v;
    for (int k = 0; k < HID; k++) {
        float wv = w2[k*HID + t];
        #pragma unroll
        for (int r = 0; r < NN; r++)
            acc2[r] = fmaf(s_h[r*HID + k], wv, acc2[r]);
    }
    #pragma unroll
    for (int r = 0; r < NN; r++) {
        float v = fmaxf(acc2[r], 0.f);
        size_t idx = (size_t)(b*NN + r)*HID + t;
        X0[idx] = v;
        split_store(v, X0h, X0l, idx);
    }
}

// -------- bf16x3 tensor-core GEMM (exact R10 version) --------
template<int DIN>
__global__ void __launch_bounds__(128, 5)
gat_gemm_bf16(const bf16* __restrict__ Xh, const bf16* __restrict__ Xl,
              const bf16* __restrict__ WLh, const bf16* __restrict__ WLl,
              const bf16* __restrict__ WRh, const bf16* __restrict__ WRl,
              float* __restrict__ GL, float* __restrict__ GR)
{
    __shared__ bf16 Ah[64][40], Al[64][40];
    __shared__ bf16 Bh[32][72], Bl[32][72];

    int mt = blockIdx.x, yt = blockIdx.y;
    const bf16* Wh = (yt < 8) ? WLh : WRh;
    const bf16* Wl = (yt < 8) ? WLl : WRl;
    float* Y = (yt < 8) ? GL : GR;
    int ct = (yt & 7) * 64;

    int t = threadIdx.x, warp = t >> 5, lane = t & 31;
    int wm = warp >> 1, wn = warp & 1;

    float d[2][4][4];
    #pragma unroll
    for (int m = 0; m < 2; m++)
        #pragma unroll
        for (int n = 0; n < 4; n++)
            #pragma unroll
            for (int r = 0; r < 4; r++) d[m][n][r] = 0.f;

    int m0 = mt * 64;
    int lk = lane & 7;
    int lt = lane >> 3;
    int a_roff = (lt & 1)*8 + lk;
    int a_koff = (lt >> 1)*8;
    int b_koff = (lt & 1)*8 + lk;
    int b_noff = (lt >> 1)*8;

    for (int kb = 0; kb < DIN; kb += 32) {
        #pragma unroll
        for (int i = t; i < 256; i += 128) {
            int r = i >> 2, c = (i & 3) * 8;
            *(uint4*)&Ah[r][c] = *(const uint4*)(Xh + (size_t)(m0 + r)*DIN + kb + c);
            *(uint4*)&Al[r][c] = *(const uint4*)(Xl + (size_t)(m0 + r)*DIN + kb + c);
        }
        #pragma unroll
        for (int i = t; i < 256; i += 128) {
            int r = i >> 3, c = (i & 7) * 8;
            *(uint4*)&Bh[r][c] = *(const uint4*)(Wh + (size_t)(kb + r)*D1 + ct + c);
            *(uint4*)&Bl[r][c] = *(const uint4*)(Wl + (size_t)(kb + r)*D1 + ct + c);
        }
        __syncthreads();

        #pragma unroll
        for (int kk = 0; kk < 2; kk++) {
            uint4 ah[2], al[2];
            #pragma unroll
            for (int m = 0; m < 2; m++) {
                int r = wm*32 + m*16 + a_roff;
                int k = kk*16 + a_koff;
                ldsm_x4(ah[m], sptr(&Ah[r][k]));
                ldsm_x4(al[m], sptr(&Al[r][k]));
            }
            uint4 bh[2], bl[2];
            #pragma unroll
            for (int p = 0; p < 2; p++) {
                int kr = kk*16 + b_koff;
                int nc = wn*32 + p*16 + b_noff;
                ldsm_x4t(bh[p], sptr(&Bh[kr][nc]));
                ldsm_x4t(bl[p], sptr(&Bl[kr][nc]));
            }
            #pragma unroll
            for (int m = 0; m < 2; m++) {
                #pragma unroll
                for (int n = 0; n < 4; n++) {
                    int p = n >> 1;
                    uint bh0 = (n & 1) ? bh[p].z : bh[p].x;
                    uint bh1 = (n & 1) ? bh[p].w : bh[p].y;
                    uint bl0 = (n & 1) ? bl[p].z : bl[p].x;
                    uint bl1 = (n & 1) ? bl[p].w : bl[p].y;
                    mma_bf16(d[m][n], ah[m].x, ah[m].y, ah[m].z, ah[m].w, bh0, bh1);
                    mma_bf16(d[m][n], ah[m].x, ah[m].y, ah[m].z, ah[m].w, bl0, bl1);
                    mma_bf16(d[m][n], al[m].x, al[m].y, al[m].z, al[m].w, bh0, bh1);
                }
            }
        }
        __syncthreads();
    }

    int g = lane >> 2, q = lane & 3;
    #pragma unroll
    for (int m = 0; m < 2; m++) {
        int row = m0 + wm*32 + m*16 + g;
        #pragma unroll
        for (int n = 0; n < 4; n++) {
            int col = ct + wn*32 + n*8 + q*2;
            *(float2*)(Y + (size_t)row*D1 + col)     = make_float2(d[m][n][0], d[m][n][1]);
            *(float2*)(Y + (size_t)(row+8)*D1 + col) = make_float2(d[m][n][2], d[m][n][3]);
        }
    }
}

// -------- GATv2 attention: R10 base + warp-per-row logits --------
template<bool SPLIT>
__global__ void attn_k(const float* __restrict__ GL, const float* __restrict__ GR,
                       const int* __restrict__ POFF,
                       const unsigned short* __restrict__ PAIRS,
                       const float* __restrict__ att, const float* __restrict__ bias,
                       float* __restrict__ Xout, bf16* __restrict__ Xouth,
                       bf16* __restrict__ Xoutl)
{
    __shared__ float gls[NN][132];
    __shared__ float grs[16][132];
    __shared__ float attv[HID];
    __shared__ float lgA[16][36];
    __shared__ float s_lgc[512];
    __shared__ unsigned short s_prs[512];
    __shared__ int s_off[17];
    __shared__ float s_A[16][2], s_B[NN][2];

    int b = blockIdx.x, h = blockIdx.y;
    int i0 = blockIdx.z * 16;
    int t = threadIdx.x, w = t >> 5, l = t & 31;

    attv[t] = att[h*HID + t];
    #pragma unroll
    for (int i = t; i < NN*(HID/4); i += 128) {
        int r = i >> 5, c4 = i & 31;
        *(float4*)&gls[r][c4*4] =
            *(const float4*)(GL + (size_t)(b*NN + r)*D1 + h*HID + c4*4);
    }
    #pragma unroll
    for (int i = t; i < 16*(HID/4); i += 128) {
        int r = i >> 5, c4 = i & 31;
        *(float4*)&grs[r][c4*4] =
            *(const float4*)(GR + (size_t)(b*NN + i0 + r)*D1 + h*HID + c4*4);
    }
    if (t < 17) s_off[t] = POFF[b*33 + i0 + t];
    #pragma unroll
    for (int i = t; i < 16*36; i += 128) (&lgA[0][0])[i] = 0.f;
    __syncthreads();

    int p0 = s_off[0];
    int Pl = s_off[16] - p0;
    for (int p = t; p < Pl; p += 128)
        s_prs[p] = PAIRS[b*NN*NN + p0 + p];

    if (t < 96) {
        int half = t & 1;
        int u = t >> 1;
        const float* row = (u < NN) ? &gls[u][0] : &grs[u - NN][0];
        float s = 0.f;
        int c4b = half * 16;
        #pragma unroll
        for (int c4 = c4b; c4 < c4b + 16; c4++) {
            float4 r4 = *(const float4*)&row[c4*4];
            float4 a4 = *(const float4*)&attv[c4*4];
            s += a4.x*r4.x + a4.y*r4.y + a4.z*r4.z + a4.w*r4.w;
        }
        if (u < NN) s_B[u][half] = s;
        else        s_A[u - NN][half] = s;
    }
    __syncthreads();

    // logits: warp w handles local rows w*4..w*4+3; lane-pair per neighbor,
    // each lane covers 64 channels. grs/attv reads are warp-broadcast.
    #pragma unroll
    for (int ii = 0; ii < 4; ii++) {
        int il = w*4 + ii;
        int seg  = s_off[il] - p0;
        int cnt  = s_off[il+1] - s_off[il];
        int half = l & 1;
        int c4b  = half * 16;
        for (int base = 0; base < cnt; base += 16) {
            int jg = base + (l >> 1);
            bool act = jg < cnt;
            float s = 0.f;
            int jj = 0;
            if (act) {
                jj = s_prs[seg + jg] & 31;
                #pragma unroll
                for (int c4 = c4b; c4 < c4b + 16; c4++) {
                    float4 gr4 = *(const float4*)&grs[il][c4*4];
                    float4 gl4 = *(const float4*)&gls[jj][c4*4];
                    float4 a4  = *(const float4*)&attv[c4*4];
                    s += a4.x * fabsf(gr4.x + gl4.x);
                    s += a4.y * fabsf(gr4.y + gl4.y);
                    s += a4.z * fabsf(gr4.z + gl4.z);
                    s += a4.w * fabsf(gr4.w + gl4.w);
                }
            }
            s += __shfl_xor_sync(0xffffffffu, s, 1);
            if (act && half == 0) {
                float A = s_A[il][0] + s_A[il][1];
                float B = s_B[jj][0] + s_B[jj][1];
                s_lgc[seg + jg] = 0.6f*(A + B) + 0.4f*s;
            }
        }
    }
    __syncthreads();

    // softmax on compact segments -> scatter alphas into dense lgA (R10)
    #pragma unroll
    for (int ii = 0; ii < 4; ii++) {
        int il = w*4 + ii;
        int seg = s_off[il] - p0;
        int cnt = s_off[il+1] - s_off[il];
        float x = (l < cnt) ? s_lgc[seg + l] : -1e30f;
        float mx = x;
        #pragma unroll
        for (int o = 16; o > 0; o >>= 1) mx = fmaxf(mx, __shfl_xor_sync(0xffffffffu, mx, o));
        float e = __expf(x - mx);
        float s = e;
        #pragma unroll
        for (int o = 16; o > 0; o >>= 1) s += __shfl_xor_sync(0xffffffffu, s, o);
        if (l < cnt) {
            int jj = s_prs[seg + l] & 31;
            lgA[il][jj] = e / s;
        }
    }
    __syncthreads();

    // dense aggregation (R10)
    float bv = bias[h*HID + t];
    #pragma unroll 4
    for (int il = 0; il < 16; il++) {
        float acc = 0.f;
        #pragma unroll
        for (int j4 = 0; j4 < 8; j4++) {
            float4 al4 = *(const float4*)&lgA[il][j4*4];
            acc = fmaf(al4.x, gls[j4*4 + 0][t], acc);
            acc = fmaf(al4.y, gls[j4*4 + 1][t], acc);
            acc = fmaf(al4.z, gls[j4*4 + 2][t], acc);
            acc = fmaf(al4.w, gls[j4*4 + 3][t], acc);
        }
        float v = fmaxf(acc + bv, 0.f);
        size_t idx = (size_t)(b*NN + i0 + il)*D1 + h*HID + t;
        Xout[idx] = v;
        if (SPLIT) split_store(v, Xouth, Xoutl, idx);
    }
}

// -------- head layer 1: GEMM with fused gather, 16-batch tiles --------
__global__ void head1_k(const float* __restrict__ obs,
                        const float* __restrict__ X0, const float* __restrict__ X1,
                        const float* __restrict__ X2,
                        const float* __restrict__ qw1, const float* __restrict__ qb1,
                        const float* __restrict__ vw1, const float* __restrict__ vb1,
                        float* __restrict__ QH, float* __restrict__ VH)
{
    __shared__ float Xs[16][65];
    __shared__ float Wsm[64][33];
    __shared__ int s_a[16];

    int mt = blockIdx.x;          // 0..7, 16 batches each
    int y  = blockIdx.y;
    const float* W  = (y < 8) ? qw1 : vw1;
    const float* Bv = (y < 8) ? qb1 : vb1;
    float* O        = (y < 8) ? QH  : VH;
    int col0 = (y & 7) * 32;

    int t = threadIdx.x;          // 256
    int cl = t & 31;
    int col = col0 + cl;
    int rr  = (t >> 5) * 2;       // 8 warps x 2 rows

    if (t < 16) {
        float av = obs[(size_t)(mt*16 + t)*OBS_W + (OBS_W - 1)];
        s_a[t] = (int)fminf(fmaxf(av, 0.f), 31.f);
    }
    __syncthreads();

    float acc[2] = {0.f, 0.f};

    for (int kb = 0; kb < LATENT; kb += 64) {
        __syncthreads();
        #pragma unroll
        for (int idx = t; idx < 16*64; idx += 256) {
            int r = idx >> 6, c = idx & 63;
            int k = kb + c;
            int a = s_a[r];
            int brow = (mt*16 + r)*NN + a;
            float v;
            if (k < HID)            v = X0[(size_t)brow*HID + k];
            else if (k < HID + D1)  v = X1[(size_t)brow*D1 + (k - HID)];
            else                    v = X2[(size_t)brow*D1 + (k - HID - D1)];
            Xs[r][c] = v;
        }
        #pragma unroll
        for (int idx = t; idx < 64*32; idx += 256) {
            int r = idx >> 5, c = idx & 31;
            Wsm[r][c] = W[(size_t)(kb + r)*DUEL_H + col0 + c];
        }
        __syncthreads();
        #pragma unroll 8
        for (int k = 0; k < 64; k++) {
            float wv = Wsm[k][cl];
            acc[0] = fmaf(Xs[rr + 0][k], wv, acc[0]);
            acc[1] = fmaf(Xs[rr + 1][k], wv, acc[1]);
        }
    }

    float bias = Bv[col];
    #pragma unroll
    for (int i = 0; i < 2; i++)
        O[(size_t)(mt*16 + rr + i)*DUEL_H + col] = fmaxf(acc[i] + bias, 0.f);
}

// -------- head layer 2 + dueling combine --------
__global__ void head2_k(const float* __restrict__ QH, const float* __restrict__ VH,
                        const float* __restrict__ qw2, const float* __restrict__ qb2,
                        const float* __restrict__ vw2, const float* __restrict__ vb2,
                        float* __restrict__ out)
{
    __shared__ float res[6];
    int b = blockIdx.x, t = threadIdx.x;
    int w = t >> 5, l = t & 31;

    float s = 0.f;
    if (w < OUTD) {
        #pragma unroll
        for (int k = l; k < DUEL_H; k += 32)
            s = fmaf(QH[b*DUEL_H + k], qw2[k*OUTD + w], s);
    } else {
        #pragma unroll
        for (int k = l; k < DUEL_H; k += 32)
            s = fmaf(VH[b*DUEL_H + k], vw2[k], s);
    }
    #pragma unroll
    for (int o = 16; o > 0; o >>= 1) s += __shfl_xor_sync(0xffffffffu, s, o);
    if (l == 0) res[w] = s + ((w < OUTD) ? qb2[w] : vb2[0]);
    __syncthreads();

    if (t < OUTD) {
        float m = (res[0] + res[1] + res[2] + res[3] + res[4]) * 0.2f;
        out[b*OUTD + t] = res[t] - m + res[5];
    }
}

extern "C" void kernel_launch(void* const* d_in, const int* in_sizes, int n_in,
                              void* d_out, int out_size)
{
    const float* obs    = (const float*)d_in[0];
    const float* enc_w1 = (const float*)d_in[1];
    const float* enc_b1 = (const float*)d_in[2];
    const float* enc_w2 = (const float*)d_in[3];
    const float* enc_b2 = (const float*)d_in[4];
    const float* wl1    = (const float*)d_in[5];
    const float* wr1    = (const float*)d_in[6];
    const float* att1   = (const float*)d_in[7];
    const float* bias1  = (const float*)d_in[8];
    const float* wl2    = (const float*)d_in[9];
    const float* wr2    = (const float*)d_in[10];
    const float* att2   = (const float*)d_in[11];
    const float* bias2  = (const float*)d_in[12];
    const float* q_w1   = (const float*)d_in[13];
    const float* q_b1   = (const float*)d_in[14];
    const float* q_w2   = (const float*)d_in[15];
    const float* q_b2   = (const float*)d_in[16];
    const float* v_w1   = (const float*)d_in[17];
    const float* v_b1   = (const float*)d_in[18];
    const float* v_w2   = (const float*)d_in[19];
    const float* v_b2   = (const float*)d_in[20];
    float* out = (float*)d_out;

    float* X0;  cudaGetSymbolAddress((void**)&X0,  g_X0);
    int* POFF;  cudaGetSymbolAddress((void**)&POFF, g_POFF);
    unsigned short* PAIRS; cudaGetSymbolAddress((void**)&PAIRS, g_PAIRS);
    float* GL1; cudaGetSymbolAddress((void**)&GL1, g_GL1);
    float* GR1; cudaGetSymbolAddress((void**)&GR1, g_GR1);
    float* X1;  cudaGetSymbolAddress((void**)&X1,  g_X1);
    float* GL2; cudaGetSymbolAddress((void**)&GL2, g_GL2);
    float* GR2; cudaGetSymbolAddress((void**)&GR2, g_GR2);
    float* X2;  cudaGetSymbolAddress((void**)&X2,  g_X2);
    float* QH;  cudaGetSymbolAddress((void**)&QH,  g_QH);
    float* VH;  cudaGetSymbolAddress((void**)&VH,  g_VH);
    bf16 *X0h, *X0l, *X1h, *X1l;
    cudaGetSymbolAddress((void**)&X0h, g_X0h);
    cudaGetSymbolAddress((void**)&X0l, g_X0l);
    cudaGetSymbolAddress((void**)&X1h, g_X1h);
    cudaGetSymbolAddress((void**)&X1l, g_X1l);
    bf16 *wl1h, *wl1l, *wr1h, *wr1l, *wl2h, *wl2l, *wr2h, *wr2l;
    cudaGetSymbolAddress((void**)&wl1h, g_wl1h);
    cudaGetSymbolAddress((void**)&wl1l, g_wl1l);
    cudaGetSymbolAddress((void**)&wr1h, g_wr1h);
    cudaGetSymbolAddress((void**)&wr1l, g_wr1l);
    cudaGetSymbolAddress((void**)&wl2h, g_wl2h);
    cudaGetSymbolAddress((void**)&wl2l, g_wl2l);
    cudaGetSymbolAddress((void**)&wr2h, g_wr2h);
    cudaGetSymbolAddress((void**)&wr2l, g_wr2l);

    split_w_k<<<(2*HID*D1 + 2*D1*D1 + 255)/256, 256>>>(wl1, wr1, wl2, wr2);

    enc_kernel<<<BS, 128>>>(obs, enc_w1, enc_b1, enc_w2, enc_b2,
                            X0, X0h, X0l, POFF, PAIRS);

    gat_gemm_bf16<HID><<<dim3(64, 16), 128>>>(X0h, X0l, wl1h, wl1l, wr1h, wr1l, GL1, GR1);
    attn_k<true><<<dim3(BS, HEADS, 2), 128>>>(GL1, GR1, POFF, PAIRS, att1, bias1,
                                              X1, X1h, X1l);

    gat_gemm_bf16<D1><<<dim3(64, 16), 128>>>(X1h, X1l, wl2h, wl2l, wr2h, wr2l, GL2, GR2);
    attn_k<false><<<dim3(BS, HEADS, 2), 128>>>(GL2, GR2, POFF, PAIRS, att2, bias2,
                                               X2, nullptr, nullptr);

    head1_k<<<dim3(8, 16), 256>>>(obs, X0, X1, X2,
                                  q_w1, q_b1, v_w1, v_b1, QH, VH);
    head2_k<<<BS, 192>>>(QH, VH, q_w2, q_b2, v_w2, v_b2, out);
}

// round 14
// speedup vs baseline: 1.2062x; 1.2062x over previous
#include <cuda_runtime.h>
#include <cuda_bf16.h>
#include <cstdint>

#define BS 128
#define NN 32
#define IN_DIM 16
#define HID 128
#define HEADS 4
#define OUTD 5
#define DUEL_H 256
#define D1 (HEADS*HID)       // 512
#define LATENT (HID + 2*D1)  // 1152
#define OBS_W (NN*(2+IN_DIM)+1) // 577
#define RAD2 0.09f

typedef unsigned int uint;
typedef __nv_bfloat16 bf16;

// -------- scratch (device globals; no runtime alloc allowed) --------
__device__ float g_X0 [BS*NN*HID];
__device__ int      g_POFF [BS*33];
__device__ unsigned short g_PAIRS[BS*NN*NN];
__device__ float g_GL1[BS*NN*D1];
__device__ float g_GR1[BS*NN*D1];
__device__ float g_X1 [BS*NN*D1];
__device__ float g_GL2[BS*NN*D1];
__device__ float g_GR2[BS*NN*D1];
__device__ float g_X2 [BS*NN*D1];
__device__ float g_QH [BS*DUEL_H];
__device__ float g_VH [BS*DUEL_H];
// bf16 hi/lo splits
__device__ bf16 g_X0h[BS*NN*HID],  g_X0l[BS*NN*HID];
__device__ bf16 g_X1h[BS*NN*D1],   g_X1l[BS*NN*D1];
__device__ bf16 g_wl1h[HID*D1], g_wl1l[HID*D1], g_wr1h[HID*D1], g_wr1l[HID*D1];
__device__ bf16 g_wl2h[D1*D1],  g_wl2l[D1*D1],  g_wr2h[D1*D1],  g_wr2l[D1*D1];

__device__ __forceinline__ uint32_t sptr(const void* p) {
    return (uint32_t)__cvta_generic_to_shared(p);
}
__device__ __forceinline__ void split_store(float v, bf16* hp, bf16* lp, size_t idx) {
    bf16 h = __float2bfloat16(v);
    hp[idx] = h;
    lp[idx] = __float2bfloat16(v - __bfloat162float(h));
}
__device__ __forceinline__ void ldsm_x4(uint4& d, uint32_t a) {
    asm volatile("ldmatrix.sync.aligned.m8n8.x4.shared.b16 {%0,%1,%2,%3}, [%4];"
        : "=r"(d.x), "=r"(d.y), "=r"(d.z), "=r"(d.w) : "r"(a));
}
__device__ __forceinline__ void ldsm_x4t(uint4& d, uint32_t a) {
    asm volatile("ldmatrix.sync.aligned.m8n8.x4.trans.shared.b16 {%0,%1,%2,%3}, [%4];"
        : "=r"(d.x), "=r"(d.y), "=r"(d.z), "=r"(d.w) : "r"(a));
}
__device__ __forceinline__ void mma_bf16(float* d,
                                         uint a0, uint a1, uint a2, uint a3,
                                         uint b0, uint b1)
{
    asm("mma.sync.aligned.m16n8k16.row.col.f32.bf16.bf16.f32 "
        "{%0,%1,%2,%3}, {%4,%5,%6,%7}, {%8,%9}, {%0,%1,%2,%3};"
        : "+f"(d[0]), "+f"(d[1]), "+f"(d[2]), "+f"(d[3])
        : "r"(a0), "r"(a1), "r"(a2), "r"(a3), "r"(b0), "r"(b1));
}

// -------- split all 4 weight matrices into bf16 hi/lo --------
__global__ void split_w_k(const float* __restrict__ wl1, const float* __restrict__ wr1,
                          const float* __restrict__ wl2, const float* __restrict__ wr2)
{
    int i = blockIdx.x*256 + threadIdx.x;
    const int S1 = HID*D1;
    const int S2 = D1*D1;
    if (i < S1)                   split_store(wl1[i],        g_wl1h, g_wl1l, i);
    else if (i < 2*S1)            split_store(wr1[i-S1],     g_wr1h, g_wr1l, i-S1);
    else if (i < 2*S1+S2)         split_store(wl2[i-2*S1],   g_wl2h, g_wl2l, i-2*S1);
    else                          split_store(wr2[i-2*S1-S2],g_wr2h, g_wr2l, i-2*S1-S2);
}

// -------- encoder + adjacency: 2 CTAs per batch, 16 rows each --------
__global__ void enc_kernel(const float* __restrict__ obs,
                           const float* __restrict__ w1, const float* __restrict__ b1,
                           const float* __restrict__ w2, const float* __restrict__ b2,
                           float* __restrict__ X0, bf16* __restrict__ X0h,
                           bf16* __restrict__ X0l,
                           int* __restrict__ POFF, unsigned short* __restrict__ PAIRS)
{
    __shared__ float s_obs[OBS_W];
    __shared__ float s_h[16*HID];
    int b = blockIdx.x, z = blockIdx.y, t = threadIdx.x;
    int r0 = z * 16;

    for (int i = t; i < OBS_W; i += 128) s_obs[i] = obs[b*OBS_W + i];
    __syncthreads();

    // adjacency + pair list: z==0 only
    if (z == 0 && t < NN) {
        float xi = s_obs[t*18 + 0], yi = s_obs[t*18 + 1];
        unsigned m = 0;
        #pragma unroll
        for (int j = 0; j < NN; j++) {
            float dx = xi - s_obs[j*18 + 0];
            float dy = yi - s_obs[j*18 + 1];
            float d2 = dx*dx + dy*dy;
            if (d2 < RAD2 || j == t) m |= (1u << j);
        }
        int c = __popc(m);
        int sc = c;
        #pragma unroll
        for (int o = 1; o < 32; o <<= 1) {
            int v = __shfl_up_sync(0xffffffffu, sc, o);
            if (t >= o) sc += v;
        }
        int off = sc - c;
        POFF[b*33 + t] = off;
        if (t == 31) POFF[b*33 + 32] = off + c;
        int k = off;
        unsigned mm = m;
        while (mm) {
            int jj = __ffs(mm) - 1;
            mm &= mm - 1;
            PAIRS[b*NN*NN + k++] = (unsigned short)((t << 5) | jj);
        }
    }

    // layer 1 for this CTA's 16 rows
    float bb = b1[t];
    for (int r = 0; r < 16; r++) {
        int row = r0 + r;
        float acc = bb;
        #pragma unroll
        for (int f = 0; f < IN_DIM; f++)
            acc += s_obs[row*18 + 2 + f] * w1[f*HID + t];
        s_h[r*HID + t] = fmaxf(acc, 0.f);
    }
    __syncthreads();

    // layer 2: 16 accumulators, w2 loaded once per k
    float acc2[16];
    float b2v = b2[t];
    #pragma unroll
    for (int r = 0; r < 16; r++) acc2[r] = b2v;
    for (int k = 0; k < HID; k++) {
        float wv = w2[k*HID + t];
        #pragma unroll
        for (int r = 0; r < 16; r++)
            acc2[r] = fmaf(s_h[r*HID + k], wv, acc2[r]);
    }
    #pragma unroll
    for (int r = 0; r < 16; r++) {
        float v = fmaxf(acc2[r], 0.f);
        size_t idx = (size_t)(b*NN + r0 + r)*HID + t;
        X0[idx] = v;
        split_store(v, X0h, X0l, idx);
    }
}

// -------- bf16x3 tensor-core GEMM (exact R10 version) --------
template<int DIN>
__global__ void __launch_bounds__(128, 5)
gat_gemm_bf16(const bf16* __restrict__ Xh, const bf16* __restrict__ Xl,
              const bf16* __restrict__ WLh, const bf16* __restrict__ WLl,
              const bf16* __restrict__ WRh, const bf16* __restrict__ WRl,
              float* __restrict__ GL, float* __restrict__ GR)
{
    __shared__ bf16 Ah[64][40], Al[64][40];
    __shared__ bf16 Bh[32][72], Bl[32][72];

    int mt = blockIdx.x, yt = blockIdx.y;
    const bf16* Wh = (yt < 8) ? WLh : WRh;
    const bf16* Wl = (yt < 8) ? WLl : WRl;
    float* Y = (yt < 8) ? GL : GR;
    int ct = (yt & 7) * 64;

    int t = threadIdx.x, warp = t >> 5, lane = t & 31;
    int wm = warp >> 1, wn = warp & 1;

    float d[2][4][4];
    #pragma unroll
    for (int m = 0; m < 2; m++)
        #pragma unroll
        for (int n = 0; n < 4; n++)
            #pragma unroll
            for (int r = 0; r < 4; r++) d[m][n][r] = 0.f;

    int m0 = mt * 64;
    int lk = lane & 7;
    int lt = lane >> 3;
    int a_roff = (lt & 1)*8 + lk;
    int a_koff = (lt >> 1)*8;
    int b_koff = (lt & 1)*8 + lk;
    int b_noff = (lt >> 1)*8;

    for (int kb = 0; kb < DIN; kb += 32) {
        #pragma unroll
        for (int i = t; i < 256; i += 128) {
            int r = i >> 2, c = (i & 3) * 8;
            *(uint4*)&Ah[r][c] = *(const uint4*)(Xh + (size_t)(m0 + r)*DIN + kb + c);
            *(uint4*)&Al[r][c] = *(const uint4*)(Xl + (size_t)(m0 + r)*DIN + kb + c);
        }
        #pragma unroll
        for (int i = t; i < 256; i += 128) {
            int r = i >> 3, c = (i & 7) * 8;
            *(uint4*)&Bh[r][c] = *(const uint4*)(Wh + (size_t)(kb + r)*D1 + ct + c);
            *(uint4*)&Bl[r][c] = *(const uint4*)(Wl + (size_t)(kb + r)*D1 + ct + c);
        }
        __syncthreads();

        #pragma unroll
        for (int kk = 0; kk < 2; kk++) {
            uint4 ah[2], al[2];
            #pragma unroll
            for (int m = 0; m < 2; m++) {
                int r = wm*32 + m*16 + a_roff;
                int k = kk*16 + a_koff;
                ldsm_x4(ah[m], sptr(&Ah[r][k]));
                ldsm_x4(al[m], sptr(&Al[r][k]));
            }
            uint4 bh[2], bl[2];
            #pragma unroll
            for (int p = 0; p < 2; p++) {
                int kr = kk*16 + b_koff;
                int nc = wn*32 + p*16 + b_noff;
                ldsm_x4t(bh[p], sptr(&Bh[kr][nc]));
                ldsm_x4t(bl[p], sptr(&Bl[kr][nc]));
            }
            #pragma unroll
            for (int m = 0; m < 2; m++) {
                #pragma unroll
                for (int n = 0; n < 4; n++) {
                    int p = n >> 1;
                    uint bh0 = (n & 1) ? bh[p].z : bh[p].x;
                    uint bh1 = (n & 1) ? bh[p].w : bh[p].y;
                    uint bl0 = (n & 1) ? bl[p].z : bl[p].x;
                    uint bl1 = (n & 1) ? bl[p].w : bl[p].y;
                    mma_bf16(d[m][n], ah[m].x, ah[m].y, ah[m].z, ah[m].w, bh0, bh1);
                    mma_bf16(d[m][n], ah[m].x, ah[m].y, ah[m].z, ah[m].w, bl0, bl1);
                    mma_bf16(d[m][n], al[m].x, al[m].y, al[m].z, al[m].w, bh0, bh1);
                }
            }
        }
        __syncthreads();
    }

    int g = lane >> 2, q = lane & 3;
    #pragma unroll
    for (int m = 0; m < 2; m++) {
        int row = m0 + wm*32 + m*16 + g;
        #pragma unroll
        for (int n = 0; n < 4; n++) {
            int col = ct + wn*32 + n*8 + q*2;
            *(float2*)(Y + (size_t)row*D1 + col)     = make_float2(d[m][n][0], d[m][n][1]);
            *(float2*)(Y + (size_t)(row+8)*D1 + col) = make_float2(d[m][n][2], d[m][n][3]);
        }
    }
}

// -------- GATv2 attention (exact R10 version) --------
template<bool SPLIT>
__global__ void attn_k(const float* __restrict__ GL, const float* __restrict__ GR,
                       const int* __restrict__ POFF,
                       const unsigned short* __restrict__ PAIRS,
                       const float* __restrict__ att, const float* __restrict__ bias,
                       float* __restrict__ Xout, bf16* __restrict__ Xouth,
                       bf16* __restrict__ Xoutl)
{
    __shared__ float gls[NN][132];
    __shared__ float grs[16][132];
    __shared__ float attv[HID];
    __shared__ float lgA[16][36];
    __shared__ float s_lgc[512];
    __shared__ unsigned short s_prs[512];
    __shared__ int s_off[17];
    __shared__ float s_A[16][2], s_B[NN][2];

    int b = blockIdx.x, h = blockIdx.y;
    int i0 = blockIdx.z * 16;
    int t = threadIdx.x, w = t >> 5, l = t & 31;

    attv[t] = att[h*HID + t];
    #pragma unroll
    for (int i = t; i < NN*(HID/4); i += 128) {
        int r = i >> 5, c4 = i & 31;
        *(float4*)&gls[r][c4*4] =
            *(const float4*)(GL + (size_t)(b*NN + r)*D1 + h*HID + c4*4);
    }
    #pragma unroll
    for (int i = t; i < 16*(HID/4); i += 128) {
        int r = i >> 5, c4 = i & 31;
        *(float4*)&grs[r][c4*4] =
            *(const float4*)(GR + (size_t)(b*NN + i0 + r)*D1 + h*HID + c4*4);
    }
    if (t < 17) s_off[t] = POFF[b*33 + i0 + t];
    #pragma unroll
    for (int i = t; i < 16*36; i += 128) (&lgA[0][0])[i] = 0.f;
    __syncthreads();

    int p0 = s_off[0];
    int Pl = s_off[16] - p0;
    for (int p = t; p < Pl; p += 128)
        s_prs[p] = PAIRS[b*NN*NN + p0 + p];

    if (t < 96) {
        int half = t & 1;
        int u = t >> 1;
        const float* row = (u < NN) ? &gls[u][0] : &grs[u - NN][0];
        float s = 0.f;
        int c4b = half * 16;
        #pragma unroll
        for (int c4 = c4b; c4 < c4b + 16; c4++) {
            float4 r4 = *(const float4*)&row[c4*4];
            float4 a4 = *(const float4*)&attv[c4*4];
            s += a4.x*r4.x + a4.y*r4.y + a4.z*r4.z + a4.w*r4.w;
        }
        if (u < NN) s_B[u][half] = s;
        else        s_A[u - NN][half] = s;
    }
    __syncthreads();

    for (int p = t; p < Pl; p += 128) {
        int pr = s_prs[p];
        int il = (pr >> 5) - i0, jj = pr & 31;
        float s = 0.f;
        #pragma unroll 8
        for (int c4 = 0; c4 < 32; c4++) {
            float4 gr4 = *(const float4*)&grs[il][c4*4];
            float4 gl4 = *(const float4*)&gls[jj][c4*4];
            float4 a4  = *(const float4*)&attv[c4*4];
            s += a4.x * fabsf(gr4.x + gl4.x);
            s += a4.y * fabsf(gr4.y + gl4.y);
            s += a4.z * fabsf(gr4.z + gl4.z);
            s += a4.w * fabsf(gr4.w + gl4.w);
        }
        float A = s_A[il][0] + s_A[il][1];
        float B = s_B[jj][0] + s_B[jj][1];
        s_lgc[p] = 0.6f*(A + B) + 0.4f*s;
    }
    __syncthreads();

    #pragma unroll
    for (int ii = 0; ii < 4; ii++) {
        int il = w*4 + ii;
        int seg = s_off[il] - p0;
        int cnt = s_off[il+1] - s_off[il];
        float x = (l < cnt) ? s_lgc[seg + l] : -1e30f;
        float mx = x;
        #pragma unroll
        for (int o = 16; o > 0; o >>= 1) mx = fmaxf(mx, __shfl_xor_sync(0xffffffffu, mx, o));
        float e = __expf(x - mx);
        float s = e;
        #pragma unroll
        for (int o = 16; o > 0; o >>= 1) s += __shfl_xor_sync(0xffffffffu, s, o);
        if (l < cnt) {
            int jj = s_prs[seg + l] & 31;
            lgA[il][jj] = e / s;
        }
    }
    __syncthreads();

    float bv = bias[h*HID + t];
    #pragma unroll 4
    for (int il = 0; il < 16; il++) {
        float acc = 0.f;
        #pragma unroll
        for (int j4 = 0; j4 < 8; j4++) {
            float4 al4 = *(const float4*)&lgA[il][j4*4];
            acc = fmaf(al4.x, gls[j4*4 + 0][t], acc);
            acc = fmaf(al4.y, gls[j4*4 + 1][t], acc);
            acc = fmaf(al4.z, gls[j4*4 + 2][t], acc);
            acc = fmaf(al4.w, gls[j4*4 + 3][t], acc);
        }
        float v = fmaxf(acc + bv, 0.f);
        size_t idx = (size_t)(b*NN + i0 + il)*D1 + h*HID + t;
        Xout[idx] = v;
        if (SPLIT) split_store(v, Xouth, Xoutl, idx);
    }
}

// -------- head layer 1 (exact R10 version) --------
__global__ void head1_k(const float* __restrict__ obs,
                        const float* __restrict__ X0, const float* __restrict__ X1,
                        const float* __restrict__ X2,
                        const float* __restrict__ qw1, const float* __restrict__ qb1,
                        const float* __restrict__ vw1, const float* __restrict__ vb1,
                        float* __restrict__ QH, float* __restrict__ VH)
{
    __shared__ float Xs[32][65];
    __shared__ float Wsm[64][33];
    __shared__ int s_a[32];

    int mt = blockIdx.x;
    int y  = blockIdx.y;
    const float* W  = (y < 8) ? qw1 : vw1;
    const float* Bv = (y < 8) ? qb1 : vb1;
    float* O        = (y < 8) ? QH  : VH;
    int col0 = (y & 7) * 32;

    int t = threadIdx.x;
    int cl = t & 31;
    int col = col0 + cl;
    int rr  = (t >> 5) * 4;

    if (t < 32) {
        float av = obs[(size_t)(mt*32 + t)*OBS_W + (OBS_W - 1)];
        s_a[t] = (int)fminf(fmaxf(av, 0.f), 31.f);
    }
    __syncthreads();

    float acc[4] = {0.f, 0.f, 0.f, 0.f};

    for (int kb = 0; kb < LATENT; kb += 64) {
        __syncthreads();
        #pragma unroll
        for (int idx = t; idx < 32*64; idx += 256) {
            int r = idx >> 6, c = idx & 63;
            int k = kb + c;
            int a = s_a[r];
            int brow = (mt*32 + r)*NN + a;
            float v;
            if (k < HID)            v = X0[(size_t)brow*HID + k];
            else if (k < HID + D1)  v = X1[(size_t)brow*D1 + (k - HID)];
            else                    v = X2[(size_t)brow*D1 + (k - HID - D1)];
            Xs[r][c] = v;
        }
        #pragma unroll
        for (int idx = t; idx < 64*32; idx += 256) {
            int r = idx >> 5, c = idx & 31;
            Wsm[r][c] = W[(size_t)(kb + r)*DUEL_H + col0 + c];
        }
        __syncthreads();
        #pragma unroll 8
        for (int k = 0; k < 64; k++) {
            float wv = Wsm[k][cl];
            acc[0] = fmaf(Xs[rr + 0][k], wv, acc[0]);
            acc[1] = fmaf(Xs[rr + 1][k], wv, acc[1]);
            acc[2] = fmaf(Xs[rr + 2][k], wv, acc[2]);
            acc[3] = fmaf(Xs[rr + 3][k], wv, acc[3]);
        }
    }

    float bias = Bv[col];
    #pragma unroll
    for (int i = 0; i < 4; i++)
        O[(size_t)(mt*32 + rr + i)*DUEL_H + col] = fmaxf(acc[i] + bias, 0.f);
}

// -------- head layer 2 + dueling combine --------
__global__ void head2_k(const float* __restrict__ QH, const float* __restrict__ VH,
                        const float* __restrict__ qw2, const float* __restrict__ qb2,
                        const float* __restrict__ vw2, const float* __restrict__ vb2,
                        float* __restrict__ out)
{
    __shared__ float res[6];
    int b = blockIdx.x, t = threadIdx.x;
    int w = t >> 5, l = t & 31;

    float s = 0.f;
    if (w < OUTD) {
        #pragma unroll
        for (int k = l; k < DUEL_H; k += 32)
            s = fmaf(QH[b*DUEL_H + k], qw2[k*OUTD + w], s);
    } else {
        #pragma unroll
        for (int k = l; k < DUEL_H; k += 32)
            s = fmaf(VH[b*DUEL_H + k], vw2[k], s);
    }
    #pragma unroll
    for (int o = 16; o > 0; o >>= 1) s += __shfl_xor_sync(0xffffffffu, s, o);
    if (l == 0) res[w] = s + ((w < OUTD) ? qb2[w] : vb2[0]);
    __syncthreads();

    if (t < OUTD) {
        float m = (res[0] + res[1] + res[2] + res[3] + res[4]) * 0.2f;
        out[b*OUTD + t] = res[t] - m + res[5];
    }
}

extern "C" void kernel_launch(void* const* d_in, const int* in_sizes, int n_in,
                              void* d_out, int out_size)
{
    const float* obs    = (const float*)d_in[0];
    const float* enc_w1 = (const float*)d_in[1];
    const float* enc_b1 = (const float*)d_in[2];
    const float* enc_w2 = (const float*)d_in[3];
    const float* enc_b2 = (const float*)d_in[4];
    const float* wl1    = (const float*)d_in[5];
    const float* wr1    = (const float*)d_in[6];
    const float* att1   = (const float*)d_in[7];
    const float* bias1  = (const float*)d_in[8];
    const float* wl2    = (const float*)d_in[9];
    const float* wr2    = (const float*)d_in[10];
    const float* att2   = (const float*)d_in[11];
    const float* bias2  = (const float*)d_in[12];
    const float* q_w1   = (const float*)d_in[13];
    const float* q_b1   = (const float*)d_in[14];
    const float* q_w2   = (const float*)d_in[15];
    const float* q_b2   = (const float*)d_in[16];
    const float* v_w1   = (const float*)d_in[17];
    const float* v_b1   = (const float*)d_in[18];
    const float* v_w2   = (const float*)d_in[19];
    const float* v_b2   = (const float*)d_in[20];
    float* out = (float*)d_out;

    float* X0;  cudaGetSymbolAddress((void**)&X0,  g_X0);
    int* POFF;  cudaGetSymbolAddress((void**)&POFF, g_POFF);
    unsigned short* PAIRS; cudaGetSymbolAddress((void**)&PAIRS, g_PAIRS);
    float* GL1; cudaGetSymbolAddress((void**)&GL1, g_GL1);
    float* GR1; cudaGetSymbolAddress((void**)&GR1, g_GR1);
    float* X1;  cudaGetSymbolAddress((void**)&X1,  g_X1);
    float* GL2; cudaGetSymbolAddress((void**)&GL2, g_GL2);
    float* GR2; cudaGetSymbolAddress((void**)&GR2, g_GR2);
    float* X2;  cudaGetSymbolAddress((void**)&X2,  g_X2);
    float* QH;  cudaGetSymbolAddress((void**)&QH,  g_QH);
    float* VH;  cudaGetSymbolAddress((void**)&VH,  g_VH);
    bf16 *X0h, *X0l, *X1h, *X1l;
    cudaGetSymbolAddress((void**)&X0h, g_X0h);
    cudaGetSymbolAddress((void**)&X0l, g_X0l);
    cudaGetSymbolAddress((void**)&X1h, g_X1h);
    cudaGetSymbolAddress((void**)&X1l, g_X1l);
    bf16 *wl1h, *wl1l, *wr1h, *wr1l, *wl2h, *wl2l, *wr2h, *wr2l;
    cudaGetSymbolAddress((void**)&wl1h, g_wl1h);
    cudaGetSymbolAddress((void**)&wl1l, g_wl1l);
    cudaGetSymbolAddress((void**)&wr1h, g_wr1h);
    cudaGetSymbolAddress((void**)&wr1l, g_wr1l);
    cudaGetSymbolAddress((void**)&wl2h, g_wl2h);
    cudaGetSymbolAddress((void**)&wl2l, g_wl2l);
    cudaGetSymbolAddress((void**)&wr2h, g_wr2h);
    cudaGetSymbolAddress((void**)&wr2l, g_wr2l);

    split_w_k<<<(2*HID*D1 + 2*D1*D1 + 255)/256, 256>>>(wl1, wr1, wl2, wr2);

    enc_kernel<<<dim3(BS, 2), 128>>>(obs, enc_w1, enc_b1, enc_w2, enc_b2,
                                     X0, X0h, X0l, POFF, PAIRS);

    gat_gemm_bf16<HID><<<dim3(64, 16), 128>>>(X0h, X0l, wl1h, wl1l, wr1h, wr1l, GL1, GR1);
    attn_k<true><<<dim3(BS, HEADS, 2), 128>>>(GL1, GR1, POFF, PAIRS, att1, bias1,
                                              X1, X1h, X1l);

    gat_gemm_bf16<D1><<<dim3(64, 16), 128>>>(X1h, X1l, wl2h, wl2l, wr2h, wr2l, GL2, GR2);
    attn_k<false><<<dim3(BS, HEADS, 2), 128>>>(GL2, GR2, POFF, PAIRS, att2, bias2,
                                               X2, nullptr, nullptr);

    head1_k<<<dim3(4, 16), 256>>>(obs, X0, X1, X2,
                                  q_w1, q_b1, v_w1, v_b1, QH, VH);
    head2_k<<<BS, 192>>>(QH, VH, q_w2, q_b2, v_w2, v_b2, out);
}

// round 15
// speedup vs baseline: 1.2398x; 1.0279x over previous
#include <cuda_runtime.h>
#include <cuda_bf16.h>
#include <cstdint>

#define BS 128
#define NN 32
#define IN_DIM 16
#define HID 128
#define HEADS 4
#define OUTD 5
#define DUEL_H 256
#define D1 (HEADS*HID)       // 512
#define LATENT (HID + 2*D1)  // 1152
#define OBS_W (NN*(2+IN_DIM)+1) // 577
#define RAD2 0.09f

typedef unsigned int uint;
typedef __nv_bfloat16 bf16;

// -------- scratch (device globals; no runtime alloc allowed) --------
__device__ float g_X0 [BS*NN*HID];
__device__ int      g_POFF [BS*33];
__device__ unsigned short g_PAIRS[BS*NN*NN];
__device__ float g_GL1[BS*NN*D1];
__device__ float g_GR1[BS*NN*D1];
__device__ float g_X1 [BS*NN*D1];
__device__ float g_GL2[BS*NN*D1];
__device__ float g_GR2[BS*NN*D1];
__device__ float g_X2 [BS*NN*D1];
__device__ float g_QH [BS*DUEL_H];
__device__ float g_VH [BS*DUEL_H];
// bf16 hi/lo splits
__device__ bf16 g_X0h[BS*NN*HID],  g_X0l[BS*NN*HID];
__device__ bf16 g_X1h[BS*NN*D1],   g_X1l[BS*NN*D1];
__device__ bf16 g_wl1h[HID*D1], g_wl1l[HID*D1], g_wr1h[HID*D1], g_wr1l[HID*D1];
__device__ bf16 g_wl2h[D1*D1],  g_wl2l[D1*D1],  g_wr2h[D1*D1],  g_wr2l[D1*D1];

__device__ __forceinline__ uint32_t sptr(const void* p) {
    return (uint32_t)__cvta_generic_to_shared(p);
}
__device__ __forceinline__ void split_store(float v, bf16* hp, bf16* lp, size_t idx) {
    bf16 h = __float2bfloat16(v);
    hp[idx] = h;
    lp[idx] = __float2bfloat16(v - __bfloat162float(h));
}
__device__ __forceinline__ void ldsm_x4(uint4& d, uint32_t a) {
    asm volatile("ldmatrix.sync.aligned.m8n8.x4.shared.b16 {%0,%1,%2,%3}, [%4];"
        : "=r"(d.x), "=r"(d.y), "=r"(d.z), "=r"(d.w) : "r"(a));
}
__device__ __forceinline__ void ldsm_x4t(uint4& d, uint32_t a) {
    asm volatile("ldmatrix.sync.aligned.m8n8.x4.trans.shared.b16 {%0,%1,%2,%3}, [%4];"
        : "=r"(d.x), "=r"(d.y), "=r"(d.z), "=r"(d.w) : "r"(a));
}
__device__ __forceinline__ void mma_bf16(float* d,
                                         uint a0, uint a1, uint a2, uint a3,
                                         uint b0, uint b1)
{
    asm("mma.sync.aligned.m16n8k16.row.col.f32.bf16.bf16.f32 "
        "{%0,%1,%2,%3}, {%4,%5,%6,%7}, {%8,%9}, {%0,%1,%2,%3};"
        : "+f"(d[0]), "+f"(d[1]), "+f"(d[2]), "+f"(d[3])
        : "r"(a0), "r"(a1), "r"(a2), "r"(a3), "r"(b0), "r"(b1));
}

// -------- split all 4 weight matrices into bf16 hi/lo --------
__global__ void split_w_k(const float* __restrict__ wl1, const float* __restrict__ wr1,
                          const float* __restrict__ wl2, const float* __restrict__ wr2)
{
    int i = blockIdx.x*256 + threadIdx.x;
    const int S1 = HID*D1;
    const int S2 = D1*D1;
    if (i < S1)                   split_store(wl1[i],        g_wl1h, g_wl1l, i);
    else if (i < 2*S1)            split_store(wr1[i-S1],     g_wr1h, g_wr1l, i-S1);
    else if (i < 2*S1+S2)         split_store(wl2[i-2*S1],   g_wl2h, g_wl2l, i-2*S1);
    else                          split_store(wr2[i-2*S1-S2],g_wr2h, g_wr2l, i-2*S1-S2);
}

// -------- encoder + adjacency: 4 CTAs per batch, 8 rows each --------
__global__ void enc_kernel(const float* __restrict__ obs,
                           const float* __restrict__ w1, const float* __restrict__ b1,
                           const float* __restrict__ w2, const float* __restrict__ b2,
                           float* __restrict__ X0, bf16* __restrict__ X0h,
                           bf16* __restrict__ X0l,
                           int* __restrict__ POFF, unsigned short* __restrict__ PAIRS)
{
    __shared__ float s_obs[OBS_W];
    __shared__ float s_h[8*HID];
    int b = blockIdx.x, z = blockIdx.y, t = threadIdx.x;
    int r0 = z * 8;

    for (int i = t; i < OBS_W; i += 128) s_obs[i] = obs[b*OBS_W + i];
    __syncthreads();

    // adjacency + pair list: z==0 only
    if (z == 0 && t < NN) {
        float xi = s_obs[t*18 + 0], yi = s_obs[t*18 + 1];
        unsigned m = 0;
        #pragma unroll
        for (int j = 0; j < NN; j++) {
            float dx = xi - s_obs[j*18 + 0];
            float dy = yi - s_obs[j*18 + 1];
            float d2 = dx*dx + dy*dy;
            if (d2 < RAD2 || j == t) m |= (1u << j);
        }
        int c = __popc(m);
        int sc = c;
        #pragma unroll
        for (int o = 1; o < 32; o <<= 1) {
            int v = __shfl_up_sync(0xffffffffu, sc, o);
            if (t >= o) sc += v;
        }
        int off = sc - c;
        POFF[b*33 + t] = off;
        if (t == 31) POFF[b*33 + 32] = off + c;
        int k = off;
        unsigned mm = m;
        while (mm) {
            int jj = __ffs(mm) - 1;
            mm &= mm - 1;
            PAIRS[b*NN*NN + k++] = (unsigned short)((t << 5) | jj);
        }
    }

    // layer 1 for this CTA's 8 rows
    float bb = b1[t];
    #pragma unroll
    for (int r = 0; r < 8; r++) {
        int row = r0 + r;
        float acc = bb;
        #pragma unroll
        for (int f = 0; f < IN_DIM; f++)
            acc += s_obs[row*18 + 2 + f] * w1[f*HID + t];
        s_h[r*HID + t] = fmaxf(acc, 0.f);
    }
    __syncthreads();

    // layer 2: 8 accumulators, w2 loaded once per k
    float acc2[8];
    float b2v = b2[t];
    #pragma unroll
    for (int r = 0; r < 8; r++) acc2[r] = b2v;
    for (int k = 0; k < HID; k++) {
        float wv = w2[k*HID + t];
        #pragma unroll
        for (int r = 0; r < 8; r++)
            acc2[r] = fmaf(s_h[r*HID + k], wv, acc2[r]);
    }
    #pragma unroll
    for (int r = 0; r < 8; r++) {
        float v = fmaxf(acc2[r], 0.f);
        size_t idx = (size_t)(b*NN + r0 + r)*HID + t;
        X0[idx] = v;
        split_store(v, X0h, X0l, idx);
    }
}

// -------- bf16x3 tensor-core GEMM (exact R10 version) --------
template<int DIN>
__global__ void __launch_bounds__(128, 5)
gat_gemm_bf16(const bf16* __restrict__ Xh, const bf16* __restrict__ Xl,
              const bf16* __restrict__ WLh, const bf16* __restrict__ WLl,
              const bf16* __restrict__ WRh, const bf16* __restrict__ WRl,
              float* __restrict__ GL, float* __restrict__ GR)
{
    __shared__ bf16 Ah[64][40], Al[64][40];
    __shared__ bf16 Bh[32][72], Bl[32][72];

    int mt = blockIdx.x, yt = blockIdx.y;
    const bf16* Wh = (yt < 8) ? WLh : WRh;
    const bf16* Wl = (yt < 8) ? WLl : WRl;
    float* Y = (yt < 8) ? GL : GR;
    int ct = (yt & 7) * 64;

    int t = threadIdx.x, warp = t >> 5, lane = t & 31;
    int wm = warp >> 1, wn = warp & 1;

    float d[2][4][4];
    #pragma unroll
    for (int m = 0; m < 2; m++)
        #pragma unroll
        for (int n = 0; n < 4; n++)
            #pragma unroll
            for (int r = 0; r < 4; r++) d[m][n][r] = 0.f;

    int m0 = mt * 64;
    int lk = lane & 7;
    int lt = lane >> 3;
    int a_roff = (lt & 1)*8 + lk;
    int a_koff = (lt >> 1)*8;
    int b_koff = (lt & 1)*8 + lk;
    int b_noff = (lt >> 1)*8;

    for (int kb = 0; kb < DIN; kb += 32) {
        #pragma unroll
        for (int i = t; i < 256; i += 128) {
            int r = i >> 2, c = (i & 3) * 8;
            *(uint4*)&Ah[r][c] = *(const uint4*)(Xh + (size_t)(m0 + r)*DIN + kb + c);
            *(uint4*)&Al[r][c] = *(const uint4*)(Xl + (size_t)(m0 + r)*DIN + kb + c);
        }
        #pragma unroll
        for (int i = t; i < 256; i += 128) {
            int r = i >> 3, c = (i & 7) * 8;
            *(uint4*)&Bh[r][c] = *(const uint4*)(Wh + (size_t)(kb + r)*D1 + ct + c);
            *(uint4*)&Bl[r][c] = *(const uint4*)(Wl + (size_t)(kb + r)*D1 + ct + c);
        }
        __syncthreads();

        #pragma unroll
        for (int kk = 0; kk < 2; kk++) {
            uint4 ah[2], al[2];
            #pragma unroll
            for (int m = 0; m < 2; m++) {
                int r = wm*32 + m*16 + a_roff;
                int k = kk*16 + a_koff;
                ldsm_x4(ah[m], sptr(&Ah[r][k]));
                ldsm_x4(al[m], sptr(&Al[r][k]));
            }
            uint4 bh[2], bl[2];
            #pragma unroll
            for (int p = 0; p < 2; p++) {
                int kr = kk*16 + b_koff;
                int nc = wn*32 + p*16 + b_noff;
                ldsm_x4t(bh[p], sptr(&Bh[kr][nc]));
                ldsm_x4t(bl[p], sptr(&Bl[kr][nc]));
            }
            #pragma unroll
            for (int m = 0; m < 2; m++) {
                #pragma unroll
                for (int n = 0; n < 4; n++) {
                    int p = n >> 1;
                    uint bh0 = (n & 1) ? bh[p].z : bh[p].x;
                    uint bh1 = (n & 1) ? bh[p].w : bh[p].y;
                    uint bl0 = (n & 1) ? bl[p].z : bl[p].x;
                    uint bl1 = (n & 1) ? bl[p].w : bl[p].y;
                    mma_bf16(d[m][n], ah[m].x, ah[m].y, ah[m].z, ah[m].w, bh0, bh1);
                    mma_bf16(d[m][n], ah[m].x, ah[m].y, ah[m].z, ah[m].w, bl0, bl1);
                    mma_bf16(d[m][n], al[m].x, al[m].y, al[m].z, al[m].w, bh0, bh1);
                }
            }
        }
        __syncthreads();
    }

    int g = lane >> 2, q = lane & 3;
    #pragma unroll
    for (int m = 0; m < 2; m++) {
        int row = m0 + wm*32 + m*16 + g;
        #pragma unroll
        for (int n = 0; n < 4; n++) {
            int col = ct + wn*32 + n*8 + q*2;
            *(float2*)(Y + (size_t)row*D1 + col)     = make_float2(d[m][n][0], d[m][n][1]);
            *(float2*)(Y + (size_t)(row+8)*D1 + col) = make_float2(d[m][n][2], d[m][n][3]);
        }
    }
}

// -------- GATv2 attention: row-split x4, 8 rows per CTA --------
template<bool SPLIT>
__global__ void attn_k(const float* __restrict__ GL, const float* __restrict__ GR,
                       const int* __restrict__ POFF,
                       const unsigned short* __restrict__ PAIRS,
                       const float* __restrict__ att, const float* __restrict__ bias,
                       float* __restrict__ Xout, bf16* __restrict__ Xouth,
                       bf16* __restrict__ Xoutl)
{
    __shared__ float gls[NN][132];
    __shared__ float grs[8][132];
    __shared__ float attv[HID];
    __shared__ float lgA[8][36];
    __shared__ float s_lgc[256];
    __shared__ unsigned short s_prs[256];
    __shared__ int s_off[9];
    __shared__ float s_A[8][2], s_B[NN][2];

    int b = blockIdx.x, h = blockIdx.y;
    int i0 = blockIdx.z * 8;
    int t = threadIdx.x, w = t >> 5, l = t & 31;

    attv[t] = att[h*HID + t];
    #pragma unroll
    for (int i = t; i < NN*(HID/4); i += 128) {
        int r = i >> 5, c4 = i & 31;
        *(float4*)&gls[r][c4*4] =
            *(const float4*)(GL + (size_t)(b*NN + r)*D1 + h*HID + c4*4);
    }
    #pragma unroll
    for (int i = t; i < 8*(HID/4); i += 128) {
        int r = i >> 5, c4 = i & 31;
        *(float4*)&grs[r][c4*4] =
            *(const float4*)(GR + (size_t)(b*NN + i0 + r)*D1 + h*HID + c4*4);
    }
    if (t < 9) s_off[t] = POFF[b*33 + i0 + t];
    #pragma unroll
    for (int i = t; i < 8*36; i += 128) (&lgA[0][0])[i] = 0.f;
    __syncthreads();

    int p0 = s_off[0];
    int Pl = s_off[8] - p0;
    for (int p = t; p < Pl; p += 128)
        s_prs[p] = PAIRS[b*NN*NN + p0 + p];

    // row dots: B_j (32 gls rows), A_i (8 grs rows), 2 halves -> 80 units
    if (t < 80) {
        int half = t & 1;
        int u = t >> 1;                  // 0..39
        const float* row = (u < NN) ? &gls[u][0] : &grs[u - NN][0];
        float s = 0.f;
        int c4b = half * 16;
        #pragma unroll
        for (int c4 = c4b; c4 < c4b + 16; c4++) {
            float4 r4 = *(const float4*)&row[c4*4];
            float4 a4 = *(const float4*)&attv[c4*4];
            s += a4.x*r4.x + a4.y*r4.y + a4.z*r4.z + a4.w*r4.w;
        }
        if (u < NN) s_B[u][half] = s;
        else        s_A[u - NN][half] = s;
    }
    __syncthreads();

    // compact logits: thread per pair
    for (int p = t; p < Pl; p += 128) {
        int pr = s_prs[p];
        int il = (pr >> 5) - i0, jj = pr & 31;
        float s = 0.f;
        #pragma unroll 8
        for (int c4 = 0; c4 < 32; c4++) {
            float4 gr4 = *(const float4*)&grs[il][c4*4];
            float4 gl4 = *(const float4*)&gls[jj][c4*4];
            float4 a4  = *(const float4*)&attv[c4*4];
            s += a4.x * fabsf(gr4.x + gl4.x);
            s += a4.y * fabsf(gr4.y + gl4.y);
            s += a4.z * fabsf(gr4.z + gl4.z);
            s += a4.w * fabsf(gr4.w + gl4.w);
        }
        float A = s_A[il][0] + s_A[il][1];
        float B = s_B[jj][0] + s_B[jj][1];
        s_lgc[p] = 0.6f*(A + B) + 0.4f*s;
    }
    __syncthreads();

    // softmax: warp w handles local rows w*2, w*2+1
    #pragma unroll
    for (int ii = 0; ii < 2; ii++) {
        int il = w*2 + ii;
        int seg = s_off[il] - p0;
        int cnt = s_off[il+1] - s_off[il];
        float x = (l < cnt) ? s_lgc[seg + l] : -1e30f;
        float mx = x;
        #pragma unroll
        for (int o = 16; o > 0; o >>= 1) mx = fmaxf(mx, __shfl_xor_sync(0xffffffffu, mx, o));
        float e = __expf(x - mx);
        float s = e;
        #pragma unroll
        for (int o = 16; o > 0; o >>= 1) s += __shfl_xor_sync(0xffffffffu, s, o);
        if (l < cnt) {
            int jj = s_prs[seg + l] & 31;
            lgA[il][jj] = e / s;
        }
    }
    __syncthreads();

    // dense aggregation: thread t = channel, 8 local rows
    float bv = bias[h*HID + t];
    #pragma unroll
    for (int il = 0; il < 8; il++) {
        float acc = 0.f;
        #pragma unroll
        for (int j4 = 0; j4 < 8; j4++) {
            float4 al4 = *(const float4*)&lgA[il][j4*4];
            acc = fmaf(al4.x, gls[j4*4 + 0][t], acc);
            acc = fmaf(al4.y, gls[j4*4 + 1][t], acc);
            acc = fmaf(al4.z, gls[j4*4 + 2][t], acc);
            acc = fmaf(al4.w, gls[j4*4 + 3][t], acc);
        }
        float v = fmaxf(acc + bv, 0.f);
        size_t idx = (size_t)(b*NN + i0 + il)*D1 + h*HID + t;
        Xout[idx] = v;
        if (SPLIT) split_store(v, Xouth, Xoutl, idx);
    }
}

// -------- head layer 1 (exact R10 version) --------
__global__ void head1_k(const float* __restrict__ obs,
                        const float* __restrict__ X0, const float* __restrict__ X1,
                        const float* __restrict__ X2,
                        const float* __restrict__ qw1, const float* __restrict__ qb1,
                        const float* __restrict__ vw1, const float* __restrict__ vb1,
                        float* __restrict__ QH, float* __restrict__ VH)
{
    __shared__ float Xs[32][65];
    __shared__ float Wsm[64][33];
    __shared__ int s_a[32];

    int mt = blockIdx.x;
    int y  = blockIdx.y;
    const float* W  = (y < 8) ? qw1 : vw1;
    const float* Bv = (y < 8) ? qb1 : vb1;
    float* O        = (y < 8) ? QH  : VH;
    int col0 = (y & 7) * 32;

    int t = threadIdx.x;
    int cl = t & 31;
    int col = col0 + cl;
    int rr  = (t >> 5) * 4;

    if (t < 32) {
        float av = obs[(size_t)(mt*32 + t)*OBS_W + (OBS_W - 1)];
        s_a[t] = (int)fminf(fmaxf(av, 0.f), 31.f);
    }
    __syncthreads();

    float acc[4] = {0.f, 0.f, 0.f, 0.f};

    for (int kb = 0; kb < LATENT; kb += 64) {
        __syncthreads();
        #pragma unroll
        for (int idx = t; idx < 32*64; idx += 256) {
            int r = idx >> 6, c = idx & 63;
            int k = kb + c;
            int a = s_a[r];
            int brow = (mt*32 + r)*NN + a;
            float v;
            if (k < HID)            v = X0[(size_t)brow*HID + k];
            else if (k < HID + D1)  v = X1[(size_t)brow*D1 + (k - HID)];
            else                    v = X2[(size_t)brow*D1 + (k - HID - D1)];
            Xs[r][c] = v;
        }
        #pragma unroll
        for (int idx = t; idx < 64*32; idx += 256) {
            int r = idx >> 5, c = idx & 31;
            Wsm[r][c] = W[(size_t)(kb + r)*DUEL_H + col0 + c];
        }
        __syncthreads();
        #pragma unroll 8
        for (int k = 0; k < 64; k++) {
            float wv = Wsm[k][cl];
            acc[0] = fmaf(Xs[rr + 0][k], wv, acc[0]);
            acc[1] = fmaf(Xs[rr + 1][k], wv, acc[1]);
            acc[2] = fmaf(Xs[rr + 2][k], wv, acc[2]);
            acc[3] = fmaf(Xs[rr + 3][k], wv, acc[3]);
        }
    }

    float bias = Bv[col];
    #pragma unroll
    for (int i = 0; i < 4; i++)
        O[(size_t)(mt*32 + rr + i)*DUEL_H + col] = fmaxf(acc[i] + bias, 0.f);
}

// -------- head layer 2 + dueling combine --------
__global__ void head2_k(const float* __restrict__ QH, const float* __restrict__ VH,
                        const float* __restrict__ qw2, const float* __restrict__ qb2,
                        const float* __restrict__ vw2, const float* __restrict__ vb2,
                        float* __restrict__ out)
{
    __shared__ float res[6];
    int b = blockIdx.x, t = threadIdx.x;
    int w = t >> 5, l = t & 31;

    float s = 0.f;
    if (w < OUTD) {
        #pragma unroll
        for (int k = l; k < DUEL_H; k += 32)
            s = fmaf(QH[b*DUEL_H + k], qw2[k*OUTD + w], s);
    } else {
        #pragma unroll
        for (int k = l; k < DUEL_H; k += 32)
            s = fmaf(VH[b*DUEL_H + k], vw2[k], s);
    }
    #pragma unroll
    for (int o = 16; o > 0; o >>= 1) s += __shfl_xor_sync(0xffffffffu, s, o);
    if (l == 0) res[w] = s + ((w < OUTD) ? qb2[w] : vb2[0]);
    __syncthreads();

    if (t < OUTD) {
        float m = (res[0] + res[1] + res[2] + res[3] + res[4]) * 0.2f;
        out[b*OUTD + t] = res[t] - m + res[5];
    }
}

extern "C" void kernel_launch(void* const* d_in, const int* in_sizes, int n_in,
                              void* d_out, int out_size)
{
    const float* obs    = (const float*)d_in[0];
    const float* enc_w1 = (const float*)d_in[1];
    const float* enc_b1 = (const float*)d_in[2];
    const float* enc_w2 = (const float*)d_in[3];
    const float* enc_b2 = (const float*)d_in[4];
    const float* wl1    = (const float*)d_in[5];
    const float* wr1    = (const float*)d_in[6];
    const float* att1   = (const float*)d_in[7];
    const float* bias1  = (const float*)d_in[8];
    const float* wl2    = (const float*)d_in[9];
    const float* wr2    = (const float*)d_in[10];
    const float* att2   = (const float*)d_in[11];
    const float* bias2  = (const float*)d_in[12];
    const float* q_w1   = (const float*)d_in[13];
    const float* q_b1   = (const float*)d_in[14];
    const float* q_w2   = (const float*)d_in[15];
    const float* q_b2   = (const float*)d_in[16];
    const float* v_w1   = (const float*)d_in[17];
    const float* v_b1   = (const float*)d_in[18];
    const float* v_w2   = (const float*)d_in[19];
    const float* v_b2   = (const float*)d_in[20];
    float* out = (float*)d_out;

    float* X0;  cudaGetSymbolAddress((void**)&X0,  g_X0);
    int* POFF;  cudaGetSymbolAddress((void**)&POFF, g_POFF);
    unsigned short* PAIRS; cudaGetSymbolAddress((void**)&PAIRS, g_PAIRS);
    float* GL1; cudaGetSymbolAddress((void**)&GL1, g_GL1);
    float* GR1; cudaGetSymbolAddress((void**)&GR1, g_GR1);
    float* X1;  cudaGetSymbolAddress((void**)&X1,  g_X1);
    float* GL2; cudaGetSymbolAddress((void**)&GL2, g_GL2);
    float* GR2; cudaGetSymbolAddress((void**)&GR2, g_GR2);
    float* X2;  cudaGetSymbolAddress((void**)&X2,  g_X2);
    float* QH;  cudaGetSymbolAddress((void**)&QH,  g_QH);
    float* VH;  cudaGetSymbolAddress((void**)&VH,  g_VH);
    bf16 *X0h, *X0l, *X1h, *X1l;
    cudaGetSymbolAddress((void**)&X0h, g_X0h);
    cudaGetSymbolAddress((void**)&X0l, g_X0l);
    cudaGetSymbolAddress((void**)&X1h, g_X1h);
    cudaGetSymbolAddress((void**)&X1l, g_X1l);
    bf16 *wl1h, *wl1l, *wr1h, *wr1l, *wl2h, *wl2l, *wr2h, *wr2l;
    cudaGetSymbolAddress((void**)&wl1h, g_wl1h);
    cudaGetSymbolAddress((void**)&wl1l, g_wl1l);
    cudaGetSymbolAddress((void**)&wr1h, g_wr1h);
    cudaGetSymbolAddress((void**)&wr1l, g_wr1l);
    cudaGetSymbolAddress((void**)&wl2h, g_wl2h);
    cudaGetSymbolAddress((void**)&wl2l, g_wl2l);
    cudaGetSymbolAddress((void**)&wr2h, g_wr2h);
    cudaGetSymbolAddress((void**)&wr2l, g_wr2l);

    split_w_k<<<(2*HID*D1 + 2*D1*D1 + 255)/256, 256>>>(wl1, wr1, wl2, wr2);

    enc_kernel<<<dim3(BS, 4), 128>>>(obs, enc_w1, enc_b1, enc_w2, enc_b2,
                                     X0, X0h, X0l, POFF, PAIRS);

    gat_gemm_bf16<HID><<<dim3(64, 16), 128>>>(X0h, X0l, wl1h, wl1l, wr1h, wr1l, GL1, GR1);
    attn_k<true><<<dim3(BS, HEADS, 4), 128>>>(GL1, GR1, POFF, PAIRS, att1, bias1,
                                              X1, X1h, X1l);

    gat_gemm_bf16<D1><<<dim3(64, 16), 128>>>(X1h, X1l, wl2h, wl2l, wr2h, wr2l, GL2, GR2);
    attn_k<false><<<dim3(BS, HEADS, 4), 128>>>(GL2, GR2, POFF, PAIRS, att2, bias2,
                                               X2, nullptr, nullptr);

    head1_k<<<dim3(4, 16), 256>>>(obs, X0, X1, X2,
                                  q_w1, q_b1, v_w1, v_b1, QH, VH);
    head2_k<<<BS, 192>>>(QH, VH, q_w2, q_b2, v_w2, v_b2, out);
}

// round 16
// speedup vs baseline: 1.2921x; 1.0422x over previous
#include <cuda_runtime.h>
#include <cuda_bf16.h>
#include <cstdint>

#define BS 128
#define NN 32
#define IN_DIM 16
#define HID 128
#define HEADS 4
#define OUTD 5
#define DUEL_H 256
#define D1 (HEADS*HID)       // 512
#define LATENT (HID + 2*D1)  // 1152
#define OBS_W (NN*(2+IN_DIM)+1) // 577
#define RAD2 0.09f

typedef unsigned int uint;
typedef __nv_bfloat16 bf16;

// -------- scratch (device globals; no runtime alloc allowed) --------
__device__ float g_X0 [BS*NN*HID];
__device__ int      g_POFF [BS*33];
__device__ unsigned short g_PAIRS[BS*NN*NN];
__device__ float g_GL1[BS*NN*D1];
__device__ float g_GR1[BS*NN*D1];
__device__ float g_X1 [BS*NN*D1];
__device__ float g_GL2[BS*NN*D1];
__device__ float g_GR2[BS*NN*D1];
__device__ float g_X2 [BS*NN*D1];
__device__ float g_QH [BS*DUEL_H];
__device__ float g_VH [BS*DUEL_H];
// bf16 hi/lo splits
__device__ bf16 g_X0h[BS*NN*HID],  g_X0l[BS*NN*HID];
__device__ bf16 g_X1h[BS*NN*D1],   g_X1l[BS*NN*D1];
__device__ bf16 g_wl1h[HID*D1], g_wl1l[HID*D1], g_wr1h[HID*D1], g_wr1l[HID*D1];
__device__ bf16 g_wl2h[D1*D1],  g_wl2l[D1*D1],  g_wr2h[D1*D1],  g_wr2l[D1*D1];

__device__ __forceinline__ uint32_t sptr(const void* p) {
    return (uint32_t)__cvta_generic_to_shared(p);
}
__device__ __forceinline__ void split_store(float v, bf16* hp, bf16* lp, size_t idx) {
    bf16 h = __float2bfloat16(v);
    hp[idx] = h;
    lp[idx] = __float2bfloat16(v - __bfloat162float(h));
}
__device__ __forceinline__ void ldsm_x4(uint4& d, uint32_t a) {
    asm volatile("ldmatrix.sync.aligned.m8n8.x4.shared.b16 {%0,%1,%2,%3}, [%4];"
        : "=r"(d.x), "=r"(d.y), "=r"(d.z), "=r"(d.w) : "r"(a));
}
__device__ __forceinline__ void ldsm_x4t(uint4& d, uint32_t a) {
    asm volatile("ldmatrix.sync.aligned.m8n8.x4.trans.shared.b16 {%0,%1,%2,%3}, [%4];"
        : "=r"(d.x), "=r"(d.y), "=r"(d.z), "=r"(d.w) : "r"(a));
}
__device__ __forceinline__ void mma_bf16(float* d,
                                         uint a0, uint a1, uint a2, uint a3,
                                         uint b0, uint b1)
{
    asm("mma.sync.aligned.m16n8k16.row.col.f32.bf16.bf16.f32 "
        "{%0,%1,%2,%3}, {%4,%5,%6,%7}, {%8,%9}, {%0,%1,%2,%3};"
        : "+f"(d[0]), "+f"(d[1]), "+f"(d[2]), "+f"(d[3])
        : "r"(a0), "r"(a1), "r"(a2), "r"(a3), "r"(b0), "r"(b1));
}

// -------- split all 4 weight matrices into bf16 hi/lo --------
__global__ void split_w_k(const float* __restrict__ wl1, const float* __restrict__ wr1,
                          const float* __restrict__ wl2, const float* __restrict__ wr2)
{
    int i = blockIdx.x*256 + threadIdx.x;
    const int S1 = HID*D1;
    const int S2 = D1*D1;
    if (i < S1)                   split_store(wl1[i],        g_wl1h, g_wl1l, i);
    else if (i < 2*S1)            split_store(wr1[i-S1],     g_wr1h, g_wr1l, i-S1);
    else if (i < 2*S1+S2)         split_store(wl2[i-2*S1],   g_wl2h, g_wl2l, i-2*S1);
    else                          split_store(wr2[i-2*S1-S2],g_wr2h, g_wr2l, i-2*S1-S2);
}

// -------- encoder + adjacency: 4 CTAs per batch, 8 rows each --------
__global__ void enc_kernel(const float* __restrict__ obs,
                           const float* __restrict__ w1, const float* __restrict__ b1,
                           const float* __restrict__ w2, const float* __restrict__ b2,
                           float* __restrict__ X0, bf16* __restrict__ X0h,
                           bf16* __restrict__ X0l,
                           int* __restrict__ POFF, unsigned short* __restrict__ PAIRS)
{
    __shared__ float s_obs[OBS_W];
    __shared__ float s_h[8*HID];
    int b = blockIdx.x, z = blockIdx.y, t = threadIdx.x;
    int r0 = z * 8;

    for (int i = t; i < OBS_W; i += 128) s_obs[i] = obs[b*OBS_W + i];
    __syncthreads();

    // adjacency + pair list: z==0 only
    if (z == 0 && t < NN) {
        float xi = s_obs[t*18 + 0], yi = s_obs[t*18 + 1];
        unsigned m = 0;
        #pragma unroll
        for (int j = 0; j < NN; j++) {
            float dx = xi - s_obs[j*18 + 0];
            float dy = yi - s_obs[j*18 + 1];
            float d2 = dx*dx + dy*dy;
            if (d2 < RAD2 || j == t) m |= (1u << j);
        }
        int c = __popc(m);
        int sc = c;
        #pragma unroll
        for (int o = 1; o < 32; o <<= 1) {
            int v = __shfl_up_sync(0xffffffffu, sc, o);
            if (t >= o) sc += v;
        }
        int off = sc - c;
        POFF[b*33 + t] = off;
        if (t == 31) POFF[b*33 + 32] = off + c;
        int k = off;
        unsigned mm = m;
        while (mm) {
            int jj = __ffs(mm) - 1;
            mm &= mm - 1;
            PAIRS[b*NN*NN + k++] = (unsigned short)((t << 5) | jj);
        }
    }

    // layer 1 for this CTA's 8 rows
    float bb = b1[t];
    #pragma unroll
    for (int r = 0; r < 8; r++) {
        int row = r0 + r;
        float acc = bb;
        #pragma unroll
        for (int f = 0; f < IN_DIM; f++)
            acc += s_obs[row*18 + 2 + f] * w1[f*HID + t];
        s_h[r*HID + t] = fmaxf(acc, 0.f);
    }
    __syncthreads();

    // layer 2: 8 accumulators, w2 loaded once per k
    float acc2[8];
    float b2v = b2[t];
    #pragma unroll
    for (int r = 0; r < 8; r++) acc2[r] = b2v;
    for (int k = 0; k < HID; k++) {
        float wv = w2[k*HID + t];
        #pragma unroll
        for (int r = 0; r < 8; r++)
            acc2[r] = fmaf(s_h[r*HID + k], wv, acc2[r]);
    }
    #pragma unroll
    for (int r = 0; r < 8; r++) {
        float v = fmaxf(acc2[r], 0.f);
        size_t idx = (size_t)(b*NN + r0 + r)*HID + t;
        X0[idx] = v;
        split_store(v, X0h, X0l, idx);
    }
}

// -------- bf16x3 tensor-core GEMM (exact R10 version) --------
template<int DIN>
__global__ void __launch_bounds__(128, 5)
gat_gemm_bf16(const bf16* __restrict__ Xh, const bf16* __restrict__ Xl,
              const bf16* __restrict__ WLh, const bf16* __restrict__ WLl,
              const bf16* __restrict__ WRh, const bf16* __restrict__ WRl,
              float* __restrict__ GL, float* __restrict__ GR)
{
    __shared__ bf16 Ah[64][40], Al[64][40];
    __shared__ bf16 Bh[32][72], Bl[32][72];

    int mt = blockIdx.x, yt = blockIdx.y;
    const bf16* Wh = (yt < 8) ? WLh : WRh;
    const bf16* Wl = (yt < 8) ? WLl : WRl;
    float* Y = (yt < 8) ? GL : GR;
    int ct = (yt & 7) * 64;

    int t = threadIdx.x, warp = t >> 5, lane = t & 31;
    int wm = warp >> 1, wn = warp & 1;

    float d[2][4][4];
    #pragma unroll
    for (int m = 0; m < 2; m++)
        #pragma unroll
        for (int n = 0; n < 4; n++)
            #pragma unroll
            for (int r = 0; r < 4; r++) d[m][n][r] = 0.f;

    int m0 = mt * 64;
    int lk = lane & 7;
    int lt = lane >> 3;
    int a_roff = (lt & 1)*8 + lk;
    int a_koff = (lt >> 1)*8;
    int b_koff = (lt & 1)*8 + lk;
    int b_noff = (lt >> 1)*8;

    for (int kb = 0; kb < DIN; kb += 32) {
        #pragma unroll
        for (int i = t; i < 256; i += 128) {
            int r = i >> 2, c = (i & 3) * 8;
            *(uint4*)&Ah[r][c] = *(const uint4*)(Xh + (size_t)(m0 + r)*DIN + kb + c);
            *(uint4*)&Al[r][c] = *(const uint4*)(Xl + (size_t)(m0 + r)*DIN + kb + c);
        }
        #pragma unroll
        for (int i = t; i < 256; i += 128) {
            int r = i >> 3, c = (i & 7) * 8;
            *(uint4*)&Bh[r][c] = *(const uint4*)(Wh + (size_t)(kb + r)*D1 + ct + c);
            *(uint4*)&Bl[r][c] = *(const uint4*)(Wl + (size_t)(kb + r)*D1 + ct + c);
        }
        __syncthreads();

        #pragma unroll
        for (int kk = 0; kk < 2; kk++) {
            uint4 ah[2], al[2];
            #pragma unroll
            for (int m = 0; m < 2; m++) {
                int r = wm*32 + m*16 + a_roff;
                int k = kk*16 + a_koff;
                ldsm_x4(ah[m], sptr(&Ah[r][k]));
                ldsm_x4(al[m], sptr(&Al[r][k]));
            }
            uint4 bh[2], bl[2];
            #pragma unroll
            for (int p = 0; p < 2; p++) {
                int kr = kk*16 + b_koff;
                int nc = wn*32 + p*16 + b_noff;
                ldsm_x4t(bh[p], sptr(&Bh[kr][nc]));
                ldsm_x4t(bl[p], sptr(&Bl[kr][nc]));
            }
            #pragma unroll
            for (int m = 0; m < 2; m++) {
                #pragma unroll
                for (int n = 0; n < 4; n++) {
                    int p = n >> 1;
                    uint bh0 = (n & 1) ? bh[p].z : bh[p].x;
                    uint bh1 = (n & 1) ? bh[p].w : bh[p].y;
                    uint bl0 = (n & 1) ? bl[p].z : bl[p].x;
                    uint bl1 = (n & 1) ? bl[p].w : bl[p].y;
                    mma_bf16(d[m][n], ah[m].x, ah[m].y, ah[m].z, ah[m].w, bh0, bh1);
                    mma_bf16(d[m][n], ah[m].x, ah[m].y, ah[m].z, ah[m].w, bl0, bl1);
                    mma_bf16(d[m][n], al[m].x, al[m].y, al[m].z, al[m].w, bh0, bh1);
                }
            }
        }
        __syncthreads();
    }

    int g = lane >> 2, q = lane & 3;
    #pragma unroll
    for (int m = 0; m < 2; m++) {
        int row = m0 + wm*32 + m*16 + g;
        #pragma unroll
        for (int n = 0; n < 4; n++) {
            int col = ct + wn*32 + n*8 + q*2;
            *(float2*)(Y + (size_t)row*D1 + col)     = make_float2(d[m][n][0], d[m][n][1]);
            *(float2*)(Y + (size_t)(row+8)*D1 + col) = make_float2(d[m][n][2], d[m][n][3]);
        }
    }
}

// -------- GATv2 attention (exact R10/R14 16-row version) --------
template<bool SPLIT>
__global__ void attn_k(const float* __restrict__ GL, const float* __restrict__ GR,
                       const int* __restrict__ POFF,
                       const unsigned short* __restrict__ PAIRS,
                       const float* __restrict__ att, const float* __restrict__ bias,
                       float* __restrict__ Xout, bf16* __restrict__ Xouth,
                       bf16* __restrict__ Xoutl)
{
    __shared__ float gls[NN][132];
    __shared__ float grs[16][132];
    __shared__ float attv[HID];
    __shared__ float lgA[16][36];
    __shared__ float s_lgc[512];
    __shared__ unsigned short s_prs[512];
    __shared__ int s_off[17];
    __shared__ float s_A[16][2], s_B[NN][2];

    int b = blockIdx.x, h = blockIdx.y;
    int i0 = blockIdx.z * 16;
    int t = threadIdx.x, w = t >> 5, l = t & 31;

    attv[t] = att[h*HID + t];
    #pragma unroll
    for (int i = t; i < NN*(HID/4); i += 128) {
        int r = i >> 5, c4 = i & 31;
        *(float4*)&gls[r][c4*4] =
            *(const float4*)(GL + (size_t)(b*NN + r)*D1 + h*HID + c4*4);
    }
    #pragma unroll
    for (int i = t; i < 16*(HID/4); i += 128) {
        int r = i >> 5, c4 = i & 31;
        *(float4*)&grs[r][c4*4] =
            *(const float4*)(GR + (size_t)(b*NN + i0 + r)*D1 + h*HID + c4*4);
    }
    if (t < 17) s_off[t] = POFF[b*33 + i0 + t];
    #pragma unroll
    for (int i = t; i < 16*36; i += 128) (&lgA[0][0])[i] = 0.f;
    __syncthreads();

    int p0 = s_off[0];
    int Pl = s_off[16] - p0;
    for (int p = t; p < Pl; p += 128)
        s_prs[p] = PAIRS[b*NN*NN + p0 + p];

    if (t < 96) {
        int half = t & 1;
        int u = t >> 1;
        const float* row = (u < NN) ? &gls[u][0] : &grs[u - NN][0];
        float s = 0.f;
        int c4b = half * 16;
        #pragma unroll
        for (int c4 = c4b; c4 < c4b + 16; c4++) {
            float4 r4 = *(const float4*)&row[c4*4];
            float4 a4 = *(const float4*)&attv[c4*4];
            s += a4.x*r4.x + a4.y*r4.y + a4.z*r4.z + a4.w*r4.w;
        }
        if (u < NN) s_B[u][half] = s;
        else        s_A[u - NN][half] = s;
    }
    __syncthreads();

    for (int p = t; p < Pl; p += 128) {
        int pr = s_prs[p];
        int il = (pr >> 5) - i0, jj = pr & 31;
        float s = 0.f;
        #pragma unroll 8
        for (int c4 = 0; c4 < 32; c4++) {
            float4 gr4 = *(const float4*)&grs[il][c4*4];
            float4 gl4 = *(const float4*)&gls[jj][c4*4];
            float4 a4  = *(const float4*)&attv[c4*4];
            s += a4.x * fabsf(gr4.x + gl4.x);
            s += a4.y * fabsf(gr4.y + gl4.y);
            s += a4.z * fabsf(gr4.z + gl4.z);
            s += a4.w * fabsf(gr4.w + gl4.w);
        }
        float A = s_A[il][0] + s_A[il][1];
        float B = s_B[jj][0] + s_B[jj][1];
        s_lgc[p] = 0.6f*(A + B) + 0.4f*s;
    }
    __syncthreads();

    #pragma unroll
    for (int ii = 0; ii < 4; ii++) {
        int il = w*4 + ii;
        int seg = s_off[il] - p0;
        int cnt = s_off[il+1] - s_off[il];
        float x = (l < cnt) ? s_lgc[seg + l] : -1e30f;
        float mx = x;
        #pragma unroll
        for (int o = 16; o > 0; o >>= 1) mx = fmaxf(mx, __shfl_xor_sync(0xffffffffu, mx, o));
        float e = __expf(x - mx);
        float s = e;
        #pragma unroll
        for (int o = 16; o > 0; o >>= 1) s += __shfl_xor_sync(0xffffffffu, s, o);
        if (l < cnt) {
            int jj = s_prs[seg + l] & 31;
            lgA[il][jj] = e / s;
        }
    }
    __syncthreads();

    float bv = bias[h*HID + t];
    #pragma unroll 4
    for (int il = 0; il < 16; il++) {
        float acc = 0.f;
        #pragma unroll
        for (int j4 = 0; j4 < 8; j4++) {
            float4 al4 = *(const float4*)&lgA[il][j4*4];
            acc = fmaf(al4.x, gls[j4*4 + 0][t], acc);
            acc = fmaf(al4.y, gls[j4*4 + 1][t], acc);
            acc = fmaf(al4.z, gls[j4*4 + 2][t], acc);
            acc = fmaf(al4.w, gls[j4*4 + 3][t], acc);
        }
        float v = fmaxf(acc + bv, 0.f);
        size_t idx = (size_t)(b*NN + i0 + il)*D1 + h*HID + t;
        Xout[idx] = v;
        if (SPLIT) split_store(v, Xouth, Xoutl, idx);
    }
}

// -------- head layer 1 (exact R10 version) --------
__global__ void head1_k(const float* __restrict__ obs,
                        const float* __restrict__ X0, const float* __restrict__ X1,
                        const float* __restrict__ X2,
                        const float* __restrict__ qw1, const float* __restrict__ qb1,
                        const float* __restrict__ vw1, const float* __restrict__ vb1,
                        float* __restrict__ QH, float* __restrict__ VH)
{
    __shared__ float Xs[32][65];
    __shared__ float Wsm[64][33];
    __shared__ int s_a[32];

    int mt = blockIdx.x;
    int y  = blockIdx.y;
    const float* W  = (y < 8) ? qw1 : vw1;
    const float* Bv = (y < 8) ? qb1 : vb1;
    float* O        = (y < 8) ? QH  : VH;
    int col0 = (y & 7) * 32;

    int t = threadIdx.x;
    int cl = t & 31;
    int col = col0 + cl;
    int rr  = (t >> 5) * 4;

    if (t < 32) {
        float av = obs[(size_t)(mt*32 + t)*OBS_W + (OBS_W - 1)];
        s_a[t] = (int)fminf(fmaxf(av, 0.f), 31.f);
    }
    __syncthreads();

    float acc[4] = {0.f, 0.f, 0.f, 0.f};

    for (int kb = 0; kb < LATENT; kb += 64) {
        __syncthreads();
        #pragma unroll
        for (int idx = t; idx < 32*64; idx += 256) {
            int r = idx >> 6, c = idx & 63;
            int k = kb + c;
            int a = s_a[r];
            int brow = (mt*32 + r)*NN + a;
            float v;
            if (k < HID)            v = X0[(size_t)brow*HID + k];
            else if (k < HID + D1)  v = X1[(size_t)brow*D1 + (k - HID)];
            else                    v = X2[(size_t)brow*D1 + (k - HID - D1)];
            Xs[r][c] = v;
        }
        #pragma unroll
        for (int idx = t; idx < 64*32; idx += 256) {
            int r = idx >> 5, c = idx & 31;
            Wsm[r][c] = W[(size_t)(kb + r)*DUEL_H + col0 + c];
        }
        __syncthreads();
        #pragma unroll 8
        for (int k = 0; k < 64; k++) {
            float wv = Wsm[k][cl];
            acc[0] = fmaf(Xs[rr + 0][k], wv, acc[0]);
            acc[1] = fmaf(Xs[rr + 1][k], wv, acc[1]);
            acc[2] = fmaf(Xs[rr + 2][k], wv, acc[2]);
            acc[3] = fmaf(Xs[rr + 3][k], wv, acc[3]);
        }
    }

    float bias = Bv[col];
    #pragma unroll
    for (int i = 0; i < 4; i++)
        O[(size_t)(mt*32 + rr + i)*DUEL_H + col] = fmaxf(acc[i] + bias, 0.f);
}

// -------- head layer 2 + dueling combine --------
__global__ void head2_k(const float* __restrict__ QH, const float* __restrict__ VH,
                        const float* __restrict__ qw2, const float* __restrict__ qb2,
                        const float* __restrict__ vw2, const float* __restrict__ vb2,
                        float* __restrict__ out)
{
    __shared__ float res[6];
    int b = blockIdx.x, t = threadIdx.x;
    int w = t >> 5, l = t & 31;

    float s = 0.f;
    if (w < OUTD) {
        #pragma unroll
        for (int k = l; k < DUEL_H; k += 32)
            s = fmaf(QH[b*DUEL_H + k], qw2[k*OUTD + w], s);
    } else {
        #pragma unroll
        for (int k = l; k < DUEL_H; k += 32)
            s = fmaf(VH[b*DUEL_H + k], vw2[k], s);
    }
    #pragma unroll
    for (int o = 16; o > 0; o >>= 1) s += __shfl_xor_sync(0xffffffffu, s, o);
    if (l == 0) res[w] = s + ((w < OUTD) ? qb2[w] : vb2[0]);
    __syncthreads();

    if (t < OUTD) {
        float m = (res[0] + res[1] + res[2] + res[3] + res[4]) * 0.2f;
        out[b*OUTD + t] = res[t] - m + res[5];
    }
}

extern "C" void kernel_launch(void* const* d_in, const int* in_sizes, int n_in,
                              void* d_out, int out_size)
{
    const float* obs    = (const float*)d_in[0];
    const float* enc_w1 = (const float*)d_in[1];
    const float* enc_b1 = (const float*)d_in[2];
    const float* enc_w2 = (const float*)d_in[3];
    const float* enc_b2 = (const float*)d_in[4];
    const float* wl1    = (const float*)d_in[5];
    const float* wr1    = (const float*)d_in[6];
    const float* att1   = (const float*)d_in[7];
    const float* bias1  = (const float*)d_in[8];
    const float* wl2    = (const float*)d_in[9];
    const float* wr2    = (const float*)d_in[10];
    const float* att2   = (const float*)d_in[11];
    const float* bias2  = (const float*)d_in[12];
    const float* q_w1   = (const float*)d_in[13];
    const float* q_b1   = (const float*)d_in[14];
    const float* q_w2   = (const float*)d_in[15];
    const float* q_b2   = (const float*)d_in[16];
    const float* v_w1   = (const float*)d_in[17];
    const float* v_b1   = (const float*)d_in[18];
    const float* v_w2   = (const float*)d_in[19];
    const float* v_b2   = (const float*)d_in[20];
    float* out = (float*)d_out;

    float* X0;  cudaGetSymbolAddress((void**)&X0,  g_X0);
    int* POFF;  cudaGetSymbolAddress((void**)&POFF, g_POFF);
    unsigned short* PAIRS; cudaGetSymbolAddress((void**)&PAIRS, g_PAIRS);
    float* GL1; cudaGetSymbolAddress((void**)&GL1, g_GL1);
    float* GR1; cudaGetSymbolAddress((void**)&GR1, g_GR1);
    float* X1;  cudaGetSymbolAddress((void**)&X1,  g_X1);
    float* GL2; cudaGetSymbolAddress((void**)&GL2, g_GL2);
    float* GR2; cudaGetSymbolAddress((void**)&GR2, g_GR2);
    float* X2;  cudaGetSymbolAddress((void**)&X2,  g_X2);
    float* QH;  cudaGetSymbolAddress((void**)&QH,  g_QH);
    float* VH;  cudaGetSymbolAddress((void**)&VH,  g_VH);
    bf16 *X0h, *X0l, *X1h, *X1l;
    cudaGetSymbolAddress((void**)&X0h, g_X0h);
    cudaGetSymbolAddress((void**)&X0l, g_X0l);
    cudaGetSymbolAddress((void**)&X1h, g_X1h);
    cudaGetSymbolAddress((void**)&X1l, g_X1l);
    bf16 *wl1h, *wl1l, *wr1h, *wr1l, *wl2h, *wl2l, *wr2h, *wr2l;
    cudaGetSymbolAddress((void**)&wl1h, g_wl1h);
    cudaGetSymbolAddress((void**)&wl1l, g_wl1l);
    cudaGetSymbolAddress((void**)&wr1h, g_wr1h);
    cudaGetSymbolAddress((void**)&wr1l, g_wr1l);
    cudaGetSymbolAddress((void**)&wl2h, g_wl2h);
    cudaGetSymbolAddress((void**)&wl2l, g_wl2l);
    cudaGetSymbolAddress((void**)&wr2h, g_wr2h);
    cudaGetSymbolAddress((void**)&wr2l, g_wr2l);

    split_w_k<<<(2*HID*D1 + 2*D1*D1 + 255)/256, 256>>>(wl1, wr1, wl2, wr2);

    enc_kernel<<<dim3(BS, 4), 128>>>(obs, enc_w1, enc_b1, enc_w2, enc_b2,
                                     X0, X0h, X0l, POFF, PAIRS);

    gat_gemm_bf16<HID><<<dim3(64, 16), 128>>>(X0h, X0l, wl1h, wl1l, wr1h, wr1l, GL1, GR1);
    attn_k<true><<<dim3(BS, HEADS, 2), 128>>>(GL1, GR1, POFF, PAIRS, att1, bias1,
                                              X1, X1h, X1l);

    gat_gemm_bf16<D1><<<dim3(64, 16), 128>>>(X1h, X1l, wl2h, wl2l, wr2h, wr2l, GL2, GR2);
    attn_k<false><<<dim3(BS, HEADS, 2), 128>>>(GL2, GR2, POFF, PAIRS, att2, bias2,
                                               X2, nullptr, nullptr);

    head1_k<<<dim3(4, 16), 256>>>(obs, X0, X1, X2,
                                  q_w1, q_b1, v_w1, v_b1, QH, VH);
    head2_k<<<BS, 192>>>(QH, VH, q_w2, q_b2, v_w2, v_b2, out);
}

// round 17
// speedup vs baseline: 1.3134x; 1.0165x over previous
#include <cuda_runtime.h>
#include <cuda_bf16.h>
#include <cstdint>

#define BS 128
#define NN 32
#define IN_DIM 16
#define HID 128
#define HEADS 4
#define OUTD 5
#define DUEL_H 256
#define D1 (HEADS*HID)       // 512
#define LATENT (HID + 2*D1)  // 1152
#define OBS_W (NN*(2+IN_DIM)+1) // 577
#define RAD2 0.09f

typedef unsigned int uint;
typedef __nv_bfloat16 bf16;

// -------- scratch (device globals; no runtime alloc allowed) --------
__device__ float g_X0 [BS*NN*HID];
__device__ int      g_POFF [BS*33];
__device__ unsigned short g_PAIRS[BS*NN*NN];
__device__ float g_GL1[BS*NN*D1];
__device__ float g_GR1[BS*NN*D1];
__device__ float g_X1 [BS*NN*D1];
__device__ float g_GL2[BS*NN*D1];
__device__ float g_GR2[BS*NN*D1];
__device__ float g_X2 [BS*NN*D1];
__device__ float g_QH [BS*DUEL_H];
__device__ float g_VH [BS*DUEL_H];
// bf16 hi/lo splits
__device__ bf16 g_X0h[BS*NN*HID],  g_X0l[BS*NN*HID];
__device__ bf16 g_X1h[BS*NN*D1],   g_X1l[BS*NN*D1];
__device__ bf16 g_wl1h[HID*D1], g_wl1l[HID*D1], g_wr1h[HID*D1], g_wr1l[HID*D1];
__device__ bf16 g_wl2h[D1*D1],  g_wl2l[D1*D1],  g_wr2h[D1*D1],  g_wr2l[D1*D1];

__device__ __forceinline__ uint32_t sptr(const void* p) {
    return (uint32_t)__cvta_generic_to_shared(p);
}
__device__ __forceinline__ void split_store(float v, bf16* hp, bf16* lp, size_t idx) {
    bf16 h = __float2bfloat16(v);
    hp[idx] = h;
    lp[idx] = __float2bfloat16(v - __bfloat162float(h));
}
__device__ __forceinline__ void ldsm_x4(uint4& d, uint32_t a) {
    asm volatile("ldmatrix.sync.aligned.m8n8.x4.shared.b16 {%0,%1,%2,%3}, [%4];"
        : "=r"(d.x), "=r"(d.y), "=r"(d.z), "=r"(d.w) : "r"(a));
}
__device__ __forceinline__ void ldsm_x4t(uint4& d, uint32_t a) {
    asm volatile("ldmatrix.sync.aligned.m8n8.x4.trans.shared.b16 {%0,%1,%2,%3}, [%4];"
        : "=r"(d.x), "=r"(d.y), "=r"(d.z), "=r"(d.w) : "r"(a));
}
__device__ __forceinline__ void mma_bf16(float* d,
                                         uint a0, uint a1, uint a2, uint a3,
                                         uint b0, uint b1)
{
    asm("mma.sync.aligned.m16n8k16.row.col.f32.bf16.bf16.f32 "
        "{%0,%1,%2,%3}, {%4,%5,%6,%7}, {%8,%9}, {%0,%1,%2,%3};"
        : "+f"(d[0]), "+f"(d[1]), "+f"(d[2]), "+f"(d[3])
        : "r"(a0), "r"(a1), "r"(a2), "r"(a3), "r"(b0), "r"(b1));
}

// -------- split all 4 weight matrices into bf16 hi/lo (float4) --------
__global__ void split_w_k(const float* __restrict__ wl1, const float* __restrict__ wr1,
                          const float* __restrict__ wl2, const float* __restrict__ wr2)
{
    int e = (blockIdx.x*256 + threadIdx.x) * 4;
    const int S1 = HID*D1;
    const int S2 = D1*D1;
    const float* src; bf16 *hp, *lp; int base;
    if (e < S1)               { src = wl1; hp = g_wl1h; lp = g_wl1l; base = 0; }
    else if (e < 2*S1)        { src = wr1; hp = g_wr1h; lp = g_wr1l; base = S1; }
    else if (e < 2*S1 + S2)   { src = wl2; hp = g_wl2h; lp = g_wl2l; base = 2*S1; }
    else                      { src = wr2; hp = g_wr2h; lp = g_wr2l; base = 2*S1 + S2; }
    int i = e - base;
    float4 v = *(const float4*)(src + i);
    split_store(v.x, hp, lp, i + 0);
    split_store(v.y, hp, lp, i + 1);
    split_store(v.z, hp, lp, i + 2);
    split_store(v.w, hp, lp, i + 3);
}

// -------- encoder + adjacency: 4 CTAs per batch, 8 rows each --------
__global__ void enc_kernel(const float* __restrict__ obs,
                           const float* __restrict__ w1, const float* __restrict__ b1,
                           const float* __restrict__ w2, const float* __restrict__ b2,
                           float* __restrict__ X0, bf16* __restrict__ X0h,
                           bf16* __restrict__ X0l,
                           int* __restrict__ POFF, unsigned short* __restrict__ PAIRS)
{
    __shared__ float s_obs[OBS_W];
    __shared__ float s_h[8*HID];
    int b = blockIdx.x, z = blockIdx.y, t = threadIdx.x;
    int r0 = z * 8;

    for (int i = t; i < OBS_W; i += 128) s_obs[i] = obs[b*OBS_W + i];
    __syncthreads();

    if (z == 0 && t < NN) {
        float xi = s_obs[t*18 + 0], yi = s_obs[t*18 + 1];
        unsigned m = 0;
        #pragma unroll
        for (int j = 0; j < NN; j++) {
            float dx = xi - s_obs[j*18 + 0];
            float dy = yi - s_obs[j*18 + 1];
            float d2 = dx*dx + dy*dy;
            if (d2 < RAD2 || j == t) m |= (1u << j);
        }
        int c = __popc(m);
        int sc = c;
        #pragma unroll
        for (int o = 1; o < 32; o <<= 1) {
            int v = __shfl_up_sync(0xffffffffu, sc, o);
            if (t >= o) sc += v;
        }
        int off = sc - c;
        POFF[b*33 + t] = off;
        if (t == 31) POFF[b*33 + 32] = off + c;
        int k = off;
        unsigned mm = m;
        while (mm) {
            int jj = __ffs(mm) - 1;
            mm &= mm - 1;
            PAIRS[b*NN*NN + k++] = (unsigned short)((t << 5) | jj);
        }
    }

    float bb = b1[t];
    #pragma unroll
    for (int r = 0; r < 8; r++) {
        int row = r0 + r;
        float acc = bb;
        #pragma unroll
        for (int f = 0; f < IN_DIM; f++)
            acc += s_obs[row*18 + 2 + f] * w1[f*HID + t];
        s_h[r*HID + t] = fmaxf(acc, 0.f);
    }
    __syncthreads();

    float acc2[8];
    float b2v = b2[t];
    #pragma unroll
    for (int r = 0; r < 8; r++) acc2[r] = b2v;
    for (int k = 0; k < HID; k++) {
        float wv = w2[k*HID + t];
        #pragma unroll
        for (int r = 0; r < 8; r++)
            acc2[r] = fmaf(s_h[r*HID + k], wv, acc2[r]);
    }
    #pragma unroll
    for (int r = 0; r < 8; r++) {
        float v = fmaxf(acc2[r], 0.f);
        size_t idx = (size_t)(b*NN + r0 + r)*HID + t;
        X0[idx] = v;
        split_store(v, X0h, X0l, idx);
    }
}

// -------- bf16x3 tensor-core GEMM, reg-staged double-buffered --------
template<int DIN>
__global__ void __launch_bounds__(128, 4)
gat_gemm_bf16(const bf16* __restrict__ Xh, const bf16* __restrict__ Xl,
              const bf16* __restrict__ WLh, const bf16* __restrict__ WLl,
              const bf16* __restrict__ WRh, const bf16* __restrict__ WRl,
              float* __restrict__ GL, float* __restrict__ GR)
{
    __shared__ bf16 Ah[2][64][40], Al[2][64][40];
    __shared__ bf16 Bh[2][32][72], Bl[2][32][72];

    int mt = blockIdx.x, yt = blockIdx.y;
    const bf16* Wh = (yt < 8) ? WLh : WRh;
    const bf16* Wl = (yt < 8) ? WLl : WRl;
    float* Y = (yt < 8) ? GL : GR;
    int ct = (yt & 7) * 64;

    int t = threadIdx.x, warp = t >> 5, lane = t & 31;
    int wm = warp >> 1, wn = warp & 1;

    float d[2][4][4];
    #pragma unroll
    for (int m = 0; m < 2; m++)
        #pragma unroll
        for (int n = 0; n < 4; n++)
            #pragma unroll
            for (int r = 0; r < 4; r++) d[m][n][r] = 0.f;

    int m0 = mt * 64;
    int lk = lane & 7;
    int lt = lane >> 3;
    int a_roff = (lt & 1)*8 + lk;
    int a_koff = (lt >> 1)*8;
    int b_koff = (lt & 1)*8 + lk;
    int b_noff = (lt >> 1)*8;

    // per-thread staging slots
    int aR[2], aC[2], bR[2], bC[2];
    #pragma unroll
    for (int s = 0; s < 2; s++) {
        int i = t + s*128;
        aR[s] = i >> 2; aC[s] = (i & 3) * 8;
        bR[s] = i >> 3; bC[s] = (i & 7) * 8;
    }

    uint4 rah[2], ral[2], rbh[2], rbl[2];
    const int NKB = DIN / 32;

    // prologue: load + store tile 0
    #pragma unroll
    for (int s = 0; s < 2; s++) {
        rah[s] = *(const uint4*)(Xh + (size_t)(m0 + aR[s])*DIN + aC[s]);
        ral[s] = *(const uint4*)(Xl + (size_t)(m0 + aR[s])*DIN + aC[s]);
        rbh[s] = *(const uint4*)(Wh + (size_t)bR[s]*D1 + ct + bC[s]);
        rbl[s] = *(const uint4*)(Wl + (size_t)bR[s]*D1 + ct + bC[s]);
    }
    #pragma unroll
    for (int s = 0; s < 2; s++) {
        *(uint4*)&Ah[0][aR[s]][aC[s]] = rah[s];
        *(uint4*)&Al[0][aR[s]][aC[s]] = ral[s];
        *(uint4*)&Bh[0][bR[s]][bC[s]] = rbh[s];
        *(uint4*)&Bl[0][bR[s]][bC[s]] = rbl[s];
    }
    __syncthreads();

    for (int it = 0; it < NKB; it++) {
        int cur = it & 1;
        // issue next tile's LDGs (latency hidden by compute below)
        if (it + 1 < NKB) {
            int kb = (it + 1) * 32;
            #pragma unroll
            for (int s = 0; s < 2; s++) {
                rah[s] = *(const uint4*)(Xh + (size_t)(m0 + aR[s])*DIN + kb + aC[s]);
                ral[s] = *(const uint4*)(Xl + (size_t)(m0 + aR[s])*DIN + kb + aC[s]);
                rbh[s] = *(const uint4*)(Wh + (size_t)(kb + bR[s])*D1 + ct + bC[s]);
                rbl[s] = *(const uint4*)(Wl + (size_t)(kb + bR[s])*D1 + ct + bC[s]);
            }
        }

        // compute current buffer
        #pragma unroll
        for (int kk = 0; kk < 2; kk++) {
            uint4 ah[2], al[2];
            #pragma unroll
            for (int m = 0; m < 2; m++) {
                int r = wm*32 + m*16 + a_roff;
                int k = kk*16 + a_koff;
                ldsm_x4(ah[m], sptr(&Ah[cur][r][k]));
                ldsm_x4(al[m], sptr(&Al[cur][r][k]));
            }
            uint4 bh[2], bl[2];
            #pragma unroll
            for (int p = 0; p < 2; p++) {
                int kr = kk*16 + b_koff;
                int nc = wn*32 + p*16 + b_noff;
                ldsm_x4t(bh[p], sptr(&Bh[cur][kr][nc]));
                ldsm_x4t(bl[p], sptr(&Bl[cur][kr][nc]));
            }
            #pragma unroll
            for (int m = 0; m < 2; m++) {
                #pragma unroll
                for (int n = 0; n < 4; n++) {
                    int p = n >> 1;
                    uint bh0 = (n & 1) ? bh[p].z : bh[p].x;
                    uint bh1 = (n & 1) ? bh[p].w : bh[p].y;
                    uint bl0 = (n & 1) ? bl[p].z : bl[p].x;
                    uint bl1 = (n & 1) ? bl[p].w : bl[p].y;
                    mma_bf16(d[m][n], ah[m].x, ah[m].y, ah[m].z, ah[m].w, bh0, bh1);
                    mma_bf16(d[m][n], ah[m].x, ah[m].y, ah[m].z, ah[m].w, bl0, bl1);
                    mma_bf16(d[m][n], al[m].x, al[m].y, al[m].z, al[m].w, bh0, bh1);
                }
            }
        }

        // store next tile into alternate buffer (safe: it was last read in it-1)
        if (it + 1 < NKB) {
            int nxt = cur ^ 1;
            #pragma unroll
            for (int s = 0; s < 2; s++) {
                *(uint4*)&Ah[nxt][aR[s]][aC[s]] = rah[s];
                *(uint4*)&Al[nxt][aR[s]][aC[s]] = ral[s];
                *(uint4*)&Bh[nxt][bR[s]][bC[s]] = rbh[s];
                *(uint4*)&Bl[nxt][bR[s]][bC[s]] = rbl[s];
            }
        }
        __syncthreads();
    }

    int g = lane >> 2, q = lane & 3;
    #pragma unroll
    for (int m = 0; m < 2; m++) {
        int row = m0 + wm*32 + m*16 + g;
        #pragma unroll
        for (int n = 0; n < 4; n++) {
            int col = ct + wn*32 + n*8 + q*2;
            *(float2*)(Y + (size_t)row*D1 + col)     = make_float2(d[m][n][0], d[m][n][1]);
            *(float2*)(Y + (size_t)(row+8)*D1 + col) = make_float2(d[m][n][2], d[m][n][3]);
        }
    }
}

// -------- GATv2 attention (exact R16 16-row version) --------
template<bool SPLIT>
__global__ void attn_k(const float* __restrict__ GL, const float* __restrict__ GR,
                       const int* __restrict__ POFF,
                       const unsigned short* __restrict__ PAIRS,
                       const float* __restrict__ att, const float* __restrict__ bias,
                       float* __restrict__ Xout, bf16* __restrict__ Xouth,
                       bf16* __restrict__ Xoutl)
{
    __shared__ float gls[NN][132];
    __shared__ float grs[16][132];
    __shared__ float attv[HID];
    __shared__ float lgA[16][36];
    __shared__ float s_lgc[512];
    __shared__ unsigned short s_prs[512];
    __shared__ int s_off[17];
    __shared__ float s_A[16][2], s_B[NN][2];

    int b = blockIdx.x, h = blockIdx.y;
    int i0 = blockIdx.z * 16;
    int t = threadIdx.x, w = t >> 5, l = t & 31;

    attv[t] = att[h*HID + t];
    #pragma unroll
    for (int i = t; i < NN*(HID/4); i += 128) {
        int r = i >> 5, c4 = i & 31;
        *(float4*)&gls[r][c4*4] =
            *(const float4*)(GL + (size_t)(b*NN + r)*D1 + h*HID + c4*4);
    }
    #pragma unroll
    for (int i = t; i < 16*(HID/4); i += 128) {
        int r = i >> 5, c4 = i & 31;
        *(float4*)&grs[r][c4*4] =
            *(const float4*)(GR + (size_t)(b*NN + i0 + r)*D1 + h*HID + c4*4);
    }
    if (t < 17) s_off[t] = POFF[b*33 + i0 + t];
    #pragma unroll
    for (int i = t; i < 16*36; i += 128) (&lgA[0][0])[i] = 0.f;
    __syncthreads();

    int p0 = s_off[0];
    int Pl = s_off[16] - p0;
    for (int p = t; p < Pl; p += 128)
        s_prs[p] = PAIRS[b*NN*NN + p0 + p];

    if (t < 96) {
        int half = t & 1;
        int u = t >> 1;
        const float* row = (u < NN) ? &gls[u][0] : &grs[u - NN][0];
        float s = 0.f;
        int c4b = half * 16;
        #pragma unroll
        for (int c4 = c4b; c4 < c4b + 16; c4++) {
            float4 r4 = *(const float4*)&row[c4*4];
            float4 a4 = *(const float4*)&attv[c4*4];
            s += a4.x*r4.x + a4.y*r4.y + a4.z*r4.z + a4.w*r4.w;
        }
        if (u < NN) s_B[u][half] = s;
        else        s_A[u - NN][half] = s;
    }
    __syncthreads();

    for (int p = t; p < Pl; p += 128) {
        int pr = s_prs[p];
        int il = (pr >> 5) - i0, jj = pr & 31;
        float s = 0.f;
        #pragma unroll 8
        for (int c4 = 0; c4 < 32; c4++) {
            float4 gr4 = *(const float4*)&grs[il][c4*4];
            float4 gl4 = *(const float4*)&gls[jj][c4*4];
            float4 a4  = *(const float4*)&attv[c4*4];
            s += a4.x * fabsf(gr4.x + gl4.x);
            s += a4.y * fabsf(gr4.y + gl4.y);
            s += a4.z * fabsf(gr4.z + gl4.z);
            s += a4.w * fabsf(gr4.w + gl4.w);
        }
        float A = s_A[il][0] + s_A[il][1];
        float B = s_B[jj][0] + s_B[jj][1];
        s_lgc[p] = 0.6f*(A + B) + 0.4f*s;
    }
    __syncthreads();

    #pragma unroll
    for (int ii = 0; ii < 4; ii++) {
        int il = w*4 + ii;
        int seg = s_off[il] - p0;
        int cnt = s_off[il+1] - s_off[il];
        float x = (l < cnt) ? s_lgc[seg + l] : -1e30f;
        float mx = x;
        #pragma unroll
        for (int o = 16; o > 0; o >>= 1) mx = fmaxf(mx, __shfl_xor_sync(0xffffffffu, mx, o));
        float e = __expf(x - mx);
        float s = e;
        #pragma unroll
        for (int o = 16; o > 0; o >>= 1) s += __shfl_xor_sync(0xffffffffu, s, o);
        if (l < cnt) {
            int jj = s_prs[seg + l] & 31;
            lgA[il][jj] = e / s;
        }
    }
    __syncthreads();

    float bv = bias[h*HID + t];
    #pragma unroll 4
    for (int il = 0; il < 16; il++) {
        float acc = 0.f;
        #pragma unroll
        for (int j4 = 0; j4 < 8; j4++) {
            float4 al4 = *(const float4*)&lgA[il][j4*4];
            acc = fmaf(al4.x, gls[j4*4 + 0][t], acc);
            acc = fmaf(al4.y, gls[j4*4 + 1][t], acc);
            acc = fmaf(al4.z, gls[j4*4 + 2][t], acc);
            acc = fmaf(al4.w, gls[j4*4 + 3][t], acc);
        }
        float v = fmaxf(acc + bv, 0.f);
        size_t idx = (size_t)(b*NN + i0 + il)*D1 + h*HID + t;
        Xout[idx] = v;
        if (SPLIT) split_store(v, Xouth, Xoutl, idx);
    }
}

// -------- head layer 1 (exact R16 version) --------
__global__ void head1_k(const float* __restrict__ obs,
                        const float* __restrict__ X0, const float* __restrict__ X1,
                        const float* __restrict__ X2,
                        const float* __restrict__ qw1, const float* __restrict__ qb1,
                        const float* __restrict__ vw1, const float* __restrict__ vb1,
                        float* __restrict__ QH, float* __restrict__ VH)
{
    __shared__ float Xs[32][65];
    __shared__ float Wsm[64][33];
    __shared__ int s_a[32];

    int mt = blockIdx.x;
    int y  = blockIdx.y;
    const float* W  = (y < 8) ? qw1 : vw1;
    const float* Bv = (y < 8) ? qb1 : vb1;
    float* O        = (y < 8) ? QH  : VH;
    int col0 = (y & 7) * 32;

    int t = threadIdx.x;
    int cl = t & 31;
    int col = col0 + cl;
    int rr  = (t >> 5) * 4;

    if (t < 32) {
        float av = obs[(size_t)(mt*32 + t)*OBS_W + (OBS_W - 1)];
        s_a[t] = (int)fminf(fmaxf(av, 0.f), 31.f);
    }
    __syncthreads();

    float acc[4] = {0.f, 0.f, 0.f, 0.f};

    for (int kb = 0; kb < LATENT; kb += 64) {
        __syncthreads();
        #pragma unroll
        for (int idx = t; idx < 32*64; idx += 256) {
            int r = idx >> 6, c = idx & 63;
            int k = kb + c;
            int a = s_a[r];
            int brow = (mt*32 + r)*NN + a;
            float v;
            if (k < HID)            v = X0[(size_t)brow*HID + k];
            else if (k < HID + D1)  v = X1[(size_t)brow*D1 + (k - HID)];
            else                    v = X2[(size_t)brow*D1 + (k - HID - D1)];
            Xs[r][c] = v;
        }
        #pragma unroll
        for (int idx = t; idx < 64*32; idx += 256) {
            int r = idx >> 5, c = idx & 31;
            Wsm[r][c] = W[(size_t)(kb + r)*DUEL_H + col0 + c];
        }
        __syncthreads();
        #pragma unroll 8
        for (int k = 0; k < 64; k++) {
            float wv = Wsm[k][cl];
            acc[0] = fmaf(Xs[rr + 0][k], wv, acc[0]);
            acc[1] = fmaf(Xs[rr + 1][k], wv, acc[1]);
            acc[2] = fmaf(Xs[rr + 2][k], wv, acc[2]);
            acc[3] = fmaf(Xs[rr + 3][k], wv, acc[3]);
        }
    }

    float bias = Bv[col];
    #pragma unroll
    for (int i = 0; i < 4; i++)
        O[(size_t)(mt*32 + rr + i)*DUEL_H + col] = fmaxf(acc[i] + bias, 0.f);
}

// -------- head layer 2 + dueling combine --------
__global__ void head2_k(const float* __restrict__ QH, const float* __restrict__ VH,
                        const float* __restrict__ qw2, const float* __restrict__ qb2,
                        const float* __restrict__ vw2, const float* __restrict__ vb2,
                        float* __restrict__ out)
{
    __shared__ float res[6];
    int b = blockIdx.x, t = threadIdx.x;
    int w = t >> 5, l = t & 31;

    float s = 0.f;
    if (w < OUTD) {
        #pragma unroll
        for (int k = l; k < DUEL_H; k += 32)
            s = fmaf(QH[b*DUEL_H + k], qw2[k*OUTD + w], s);
    } else {
        #pragma unroll
        for (int k = l; k < DUEL_H; k += 32)
            s = fmaf(VH[b*DUEL_H + k], vw2[k], s);
    }
    #pragma unroll
    for (int o = 16; o > 0; o >>= 1) s += __shfl_xor_sync(0xffffffffu, s, o);
    if (l == 0) res[w] = s + ((w < OUTD) ? qb2[w] : vb2[0]);
    __syncthreads();

    if (t < OUTD) {
        float m = (res[0] + res[1] + res[2] + res[3] + res[4]) * 0.2f;
        out[b*OUTD + t] = res[t] - m + res[5];
    }
}

extern "C" void kernel_launch(void* const* d_in, const int* in_sizes, int n_in,
                              void* d_out, int out_size)
{
    const float* obs    = (const float*)d_in[0];
    const float* enc_w1 = (const float*)d_in[1];
    const float* enc_b1 = (const float*)d_in[2];
    const float* enc_w2 = (const float*)d_in[3];
    const float* enc_b2 = (const float*)d_in[4];
    const float* wl1    = (const float*)d_in[5];
    const float* wr1    = (const float*)d_in[6];
    const float* att1   = (const float*)d_in[7];
    const float* bias1  = (const float*)d_in[8];
    const float* wl2    = (const float*)d_in[9];
    const float* wr2    = (const float*)d_in[10];
    const float* att2   = (const float*)d_in[11];
    const float* bias2  = (const float*)d_in[12];
    const float* q_w1   = (const float*)d_in[13];
    const float* q_b1   = (const float*)d_in[14];
    const float* q_w2   = (const float*)d_in[15];
    const float* q_b2   = (const float*)d_in[16];
    const float* v_w1   = (const float*)d_in[17];
    const float* v_b1   = (const float*)d_in[18];
    const float* v_w2   = (const float*)d_in[19];
    const float* v_b2   = (const float*)d_in[20];
    float* out = (float*)d_out;

    float* X0;  cudaGetSymbolAddress((void**)&X0,  g_X0);
    int* POFF;  cudaGetSymbolAddress((void**)&POFF, g_POFF);
    unsigned short* PAIRS; cudaGetSymbolAddress((void**)&PAIRS, g_PAIRS);
    float* GL1; cudaGetSymbolAddress((void**)&GL1, g_GL1);
    float* GR1; cudaGetSymbolAddress((void**)&GR1, g_GR1);
    float* X1;  cudaGetSymbolAddress((void**)&X1,  g_X1);
    float* GL2; cudaGetSymbolAddress((void**)&GL2, g_GL2);
    float* GR2; cudaGetSymbolAddress((void**)&GR2, g_GR2);
    float* X2;  cudaGetSymbolAddress((void**)&X2,  g_X2);
    float* QH;  cudaGetSymbolAddress((void**)&QH,  g_QH);
    float* VH;  cudaGetSymbolAddress((void**)&VH,  g_VH);
    bf16 *X0h, *X0l, *X1h, *X1l;
    cudaGetSymbolAddress((void**)&X0h, g_X0h);
    cudaGetSymbolAddress((void**)&X0l, g_X0l);
    cudaGetSymbolAddress((void**)&X1h, g_X1h);
    cudaGetSymbolAddress((void**)&X1l, g_X1l);
    bf16 *wl1h, *wl1l, *wr1h, *wr1l, *wl2h, *wl2l, *wr2h, *wr2l;
    cudaGetSymbolAddress((void**)&wl1h, g_wl1h);
    cudaGetSymbolAddress((void**)&wl1l, g_wl1l);
    cudaGetSymbolAddress((void**)&wr1h, g_wr1h);
    cudaGetSymbolAddress((void**)&wr1l, g_wr1l);
    cudaGetSymbolAddress((void**)&wl2h, g_wl2h);
    cudaGetSymbolAddress((void**)&wl2l, g_wl2l);
    cudaGetSymbolAddress((void**)&wr2h, g_wr2h);
    cudaGetSymbolAddress((void**)&wr2l, g_wr2l);

    split_w_k<<<640, 256>>>(wl1, wr1, wl2, wr2);

    enc_kernel<<<dim3(BS, 4), 128>>>(obs, enc_w1, enc_b1, enc_w2, enc_b2,
                                     X0, X0h, X0l, POFF, PAIRS);

    gat_gemm_bf16<HID><<<dim3(64, 16), 128>>>(X0h, X0l, wl1h, wl1l, wr1h, wr1l, GL1, GR1);
    attn_k<true><<<dim3(BS, HEADS, 2), 128>>>(GL1, GR1, POFF, PAIRS, att1, bias1,
                                              X1, X1h, X1l);

    gat_gemm_bf16<D1><<<dim3(64, 16), 128>>>(X1h, X1l, wl2h, wl2l, wr2h, wr2l, GL2, GR2);
    attn_k<false><<<dim3(BS, HEADS, 2), 128>>>(GL2, GR2, POFF, PAIRS, att2, bias2,
                                               X2, nullptr, nullptr);

    head1_k<<<dim3(4, 16), 256>>>(obs, X0, X1, X2,
                                  q_w1, q_b1, v_w1, v_b1, QH, VH);
    head2_k<<<BS, 192>>>(QH, VH, q_w2, q_b2, v_w2, v_b2, out);
}